// round 13
// baseline (speedup 1.0000x reference)
#include <cuda_runtime.h>
#include <cuda_fp16.h>
#include <math.h>
#include <stdint.h>

#define BSZ 32
#define SEQ 2048
#define DIM 512
#define DGLU 1024
#define MROWS (BSZ * SEQ)
#define SCAN_TS 32
#define SCAN_CH (SEQ / SCAN_TS)    // 64
#define CHN ((size_t)BSZ * SCAN_CH * DIM)

#define HROW 72
#define TILEH (128 * HROW)
#define STAGEH (2 * TILEH)
#define NSTAGE 3
#define SMEM_BYTES (NSTAGE * STAGEH * 2)   // 110592

__device__ float g_bufA[(size_t)MROWS * DIM];
__device__ float g_bufB[(size_t)MROWS * DIM];
__device__ float g_bufC[(size_t)MROWS * DIM];
__device__ float g_bufD[(size_t)MROWS * DIM];
__device__ float g_bufE[(size_t)MROWS * DGLU];
__device__ float g_bufF[(size_t)MROWS * DGLU];
__device__ float g_WT[1312768];

__device__ __forceinline__ float sigmoidf_(float v) { return 1.f / (1.f + expf(-v)); }

enum { MODE_PLAIN = 0, MODE_GLU = 1, MODE_TRI = 2 };

__device__ __forceinline__ void mma_f16(float* d, const uint32_t* a, const uint32_t* b) {
    asm volatile("mma.sync.aligned.m16n8k16.row.col.f32.f16.f16.f32 "
                 "{%0,%1,%2,%3}, {%4,%5,%6,%7}, {%8,%9}, {%0,%1,%2,%3};"
                 : "+f"(d[0]), "+f"(d[1]), "+f"(d[2]), "+f"(d[3])
                 : "r"(a[0]), "r"(a[1]), "r"(a[2]), "r"(a[3]), "r"(b[0]), "r"(b[1]));
}
__device__ __forceinline__ void cpasync16(uint32_t dst, const void* src) {
    asm volatile("cp.async.cg.shared.global [%0], [%1], 16;" :: "r"(dst), "l"(src));
}
__device__ __forceinline__ uint32_t smem_u32(const void* p) {
    uint32_t a;
    asm("{ .reg .u64 t; cvta.to.shared.u64 t, %1; cvt.u32.u64 %0, t; }" : "=r"(a) : "l"(p));
    return a;
}

__device__ __forceinline__ void stage_in(uint32_t smem_stage_u, const __half* Ab, const __half* Bb,
                                         int K, int kc, int tid) {
#pragma unroll
    for (int i = 0; i < 8; i++) {
        const int idx = tid + i * 256;
        const int mat = idx >> 10;
        const int r   = (idx >> 3) & 127;
        const int c8  = idx & 7;
        const __half* src = (mat ? Bb : Ab) + (size_t)r * K + kc * 64 + c8 * 8;
        const uint32_t dst = smem_stage_u + (uint32_t)(mat * TILEH + r * HROW + c8 * 8) * 2u;
        cpasync16(dst, src);
    }
}

// C[M,N] = epilogue(A[M,K] @ WT[N,K]^T + bias); BK=64, 3-stage, one barrier/chunk
template <int MODE>
__global__ __launch_bounds__(256)
void tc_gemm(const __half* __restrict__ A, const __half* __restrict__ WT,
             const float* __restrict__ bias, void* __restrict__ Cv,
             float* __restrict__ C1, float* __restrict__ C2,
             const float* __restrict__ aux, const float* __restrict__ lbp, int N, int K)
{
    extern __shared__ __half sm[];

    const int tid = threadIdx.x, wid = tid >> 5, lane = tid & 31;
    const int g = lane >> 2, cc = lane & 3;
    const int bm = blockIdx.y * 128;
    const int wm = (wid >> 2) * 64, wn = (wid & 3) * 32;
    const uint32_t sm_u = smem_u32(sm);

    const __half* Ab = A + (size_t)bm * K;
    const __half* Bb = WT + (size_t)blockIdx.x * 128 * K;
    const int NK = K >> 6;

    float acc[4][4][4];
#pragma unroll
    for (int mf = 0; mf < 4; mf++)
#pragma unroll
        for (int nf = 0; nf < 4; nf++)
#pragma unroll
            for (int k = 0; k < 4; k++) acc[mf][nf][k] = 0.f;

    stage_in(sm_u, Ab, Bb, K, 0, tid);
    asm volatile("cp.async.commit_group;");
    if (NK > 1) {
        stage_in(sm_u + STAGEH * 2, Ab, Bb, K, 1, tid);
        asm volatile("cp.async.commit_group;");
    }

    int sidx = 0;
    for (int kc = 0; kc < NK; kc++) {
        asm volatile("cp.async.wait_group 1;");
        __syncthreads();
        if (kc + 2 < NK) {
            int ps = sidx + 2; if (ps >= NSTAGE) ps -= NSTAGE;
            stage_in(sm_u + ps * STAGEH * 2, Ab, Bb, K, kc + 2, tid);
            asm volatile("cp.async.commit_group;");
        } else {
            asm volatile("cp.async.commit_group;");
        }

        const __half* As = sm + sidx * STAGEH;
        const __half* Bs = As + TILEH;
#pragma unroll
        for (int ks = 0; ks < 4; ks++) {
            uint32_t af[4][4], bf[4][2];
#pragma unroll
            for (int mf = 0; mf < 4; mf++) {
                const __half* p = As + (wm + mf * 16 + g) * HROW + ks * 16 + cc * 2;
                af[mf][0] = *(const uint32_t*)(p);
                af[mf][1] = *(const uint32_t*)(p + 8 * HROW);
                af[mf][2] = *(const uint32_t*)(p + 8);
                af[mf][3] = *(const uint32_t*)(p + 8 * HROW + 8);
            }
#pragma unroll
            for (int nf = 0; nf < 4; nf++) {
                const __half* q = Bs + (wn + nf * 8 + g) * HROW + ks * 16 + cc * 2;
                bf[nf][0] = *(const uint32_t*)(q);
                bf[nf][1] = *(const uint32_t*)(q + 8);
            }
#pragma unroll
            for (int mf = 0; mf < 4; mf++)
#pragma unroll
                for (int nf = 0; nf < 4; nf++)
                    mma_f16(acc[mf][nf], af[mf], bf[nf]);
        }
        if (++sidx == NSTAGE) sidx = 0;
    }

    int seg = 0, bnl = blockIdx.x * 128;
    float* Cout = (float*)Cv;
    float lb = 0.f;
    if (MODE == MODE_TRI) {
        seg = blockIdx.x >> 2;
        bnl = (blockIdx.x & 3) * 128;
        Cout = (seg == 0) ? (float*)Cv : (seg == 1 ? C1 : C2);
        if (seg == 0) lb = __ldg(lbp);
    }

#pragma unroll
    for (int mf = 0; mf < 4; mf++) {
#pragma unroll
        for (int half_ = 0; half_ < 2; half_++) {
            const int row = bm + wm + mf * 16 + g + half_ * 8;
            const float* Arow = (MODE == MODE_GLU) ? aux + (size_t)row * N : nullptr;
#pragma unroll
            for (int nf = 0; nf < 4; nf++) {
                const int col = bnl + wn + nf * 8 + cc * 2;
                const float2 bb = *(const float2*)&bias[blockIdx.x * 128 + wn + nf * 8 + cc * 2];
                float v0 = acc[mf][nf][half_ * 2 + 0] + bb.x;
                float v1 = acc[mf][nf][half_ * 2 + 1] + bb.y;
                float o0 = v0, o1 = v1;
                if (MODE == MODE_TRI) {
                    if (seg == 0) {
                        o0 = lb + (1.f - lb) * sigmoidf_(v0);
                        o1 = lb + (1.f - lb) * sigmoidf_(v1);
                    } else if (seg == 2) {
                        o0 = sigmoidf_(v0); o1 = sigmoidf_(v1);
                    }
                } else if (MODE == MODE_GLU) {
                    const float2 ax = *(const float2*)(Arow + col);
                    o0 = (v0 * sigmoidf_(v0)) * ax.x;
                    o1 = (v1 * sigmoidf_(v1)) * ax.y;
                }
                if (MODE == MODE_GLU) {
                    __half2 h2 = __floats2half2_rn(o0, o1);
                    *(__half2*)((__half*)Cv + (size_t)row * N + col) = h2;
                } else {
                    float2 o; o.x = o0; o.y = o1;
                    *(float2*)(Cout + (size_t)row * N + col) = o;
                }
            }
        }
    }
}

__global__ void transpose_all(const float* __restrict__ s0, const float* __restrict__ s1,
                              const float* __restrict__ s2, const float* __restrict__ s3,
                              const float* __restrict__ s4, const float* __restrict__ s5,
                              const float* __restrict__ s6, __half* __restrict__ wh)
{
    __shared__ float tile[32][33];
    const int bid = blockIdx.x;
    const float* src; __half* dst; int K, N, ti;
    if (bid < 1024) {
        const int j = bid >> 8; ti = bid & 255;
        src = (j == 0) ? s0 : (j == 1) ? s1 : (j == 2) ? s2 : s3;
        dst = wh + (size_t)j * 262144; K = DIM; N = DIM;
    } else if (bid < 2048) {
        const int j = (bid - 1024) >> 9; ti = (bid - 1024) & 511;
        src = j ? s5 : s4;
        dst = wh + 1048576 + (size_t)j * 524288; K = DIM; N = DGLU;
    } else {
        ti = bid - 2048;
        src = s6; dst = wh + 2097152; K = DGLU; N = DIM;
    }
    const int ntx = N >> 5;
    const int n0 = (ti % ntx) * 32, k0 = (ti / ntx) * 32;
    for (int i = threadIdx.y; i < 32; i += 8)
        tile[i][threadIdx.x] = src[(size_t)(k0 + i) * N + n0 + threadIdx.x];
    __syncthreads();
    for (int i = threadIdx.y; i < 32; i += 8)
        dst[(size_t)(n0 + i) * K + k0 + threadIdx.x] = __float2half_rn(tile[threadIdx.x][i]);
}

__global__ void round_xh(const float* __restrict__ src, __half* __restrict__ dst) {
    const size_t i = (size_t)blockIdx.x * blockDim.x + threadIdx.x;
    float4 v = *(const float4*)(src + i * 4);
    __half2 a = __floats2half2_rn(v.x, v.y);
    __half2 b = __floats2half2_rn(v.z, v.w);
    uint2 u; u.x = *(uint32_t*)&a; u.y = *(uint32_t*)&b;
    *(uint2*)(dst + i * 4) = u;
}

__global__ void bias_cat(const float* __restrict__ b0, const float* __restrict__ b1,
                         const float* __restrict__ b2, float* __restrict__ dst) {
    const int i = blockIdx.x * blockDim.x + threadIdx.x;
    if (i < DIM) dst[i] = b0[i];
    else if (i < 2 * DIM) dst[i] = b1[i - DIM];
    else if (i < 3 * DIM) dst[i] = b2[i - 2 * DIM];
}

// pass1: chunk summaries only; lam/u cached in registers
__global__ __launch_bounds__(512)
void scan_pass1(const float* __restrict__ lam, const float* __restrict__ iraw,
                float* __restrict__ prod, float* __restrict__ lastF, float* __restrict__ lastB)
{
    const int b = blockIdx.x >> 6, ch = blockIdx.x & 63;
    const int d = threadIdx.x;
    const size_t base = ((size_t)b * SEQ + ch * SCAN_TS) * DIM + d;
    float la[SCAN_TS], uu[SCAN_TS];
#pragma unroll
    for (int t = 0; t < SCAN_TS; t++) {
        const size_t ix = base + (size_t)t * DIM;
        const float l = lam[ix], iv = iraw[ix];
        la[t] = l;
        uu[t] = (1.f - l) * (iv * sigmoidf_(iv));
    }
    float hf = 0.f, p = 1.f, hb = 0.f;
#pragma unroll
    for (int t = 0; t < SCAN_TS; t++) { hf = fmaf(la[t], hf, uu[t]); p *= la[t]; }
#pragma unroll
    for (int t = SCAN_TS - 1; t >= 0; t--) hb = fmaf(la[t], hb, uu[t]);
    const size_t ci = ((size_t)b * SCAN_CH + ch) * DIM + d;
    prod[ci] = p; lastF[ci] = hf; lastB[ci] = hb;
}

__global__ void scan_pass2(const float* __restrict__ prod, const float* __restrict__ lastF,
                           const float* __restrict__ lastB, float* __restrict__ CF, float* __restrict__ CB)
{
    const int c = blockIdx.x * blockDim.x + threadIdx.x;
    if (c >= BSZ * DIM) return;
    const int b = c >> 9, d = c & 511;
    float cf = 0.f;
#pragma unroll 4
    for (int ch = 0; ch < SCAN_CH; ch++) {
        const size_t i = ((size_t)b * SCAN_CH + ch) * DIM + d;
        CF[i] = cf; cf = fmaf(prod[i], cf, lastF[i]);
    }
    float cb = 0.f;
#pragma unroll 4
    for (int ch = SCAN_CH - 1; ch >= 0; ch--) {
        const size_t i = ((size_t)b * SCAN_CH + ch) * DIM + d;
        CB[i] = cb; cb = fmaf(prod[i], cb, lastB[i]);
    }
}

// pass3: recompute local scans in regs, combine carries, fused rmsnorm*gate -> half
__global__ __launch_bounds__(512)
void scan_pass3_rms(const float* __restrict__ lam, const float* __restrict__ iraw,
                    const float* __restrict__ CF, const float* __restrict__ CB,
                    const float* __restrict__ g, __half* __restrict__ out)
{
    __shared__ float red[SCAN_TS][17];
    __shared__ float tot[SCAN_TS];
    const int b = blockIdx.x >> 6, ch = blockIdx.x & 63;
    const int d = threadIdx.x, wid = d >> 5, lane = d & 31;
    const size_t base = ((size_t)b * SEQ + ch * SCAN_TS) * DIM + d;
    const size_t ci = ((size_t)b * SCAN_CH + ch) * DIM + d;
    const float cf = CF[ci], cb = CB[ci];

    float la[SCAN_TS], uu[SCAN_TS], vals[SCAN_TS];
#pragma unroll
    for (int t = 0; t < SCAN_TS; t++) {
        const size_t ix = base + (size_t)t * DIM;
        const float l = lam[ix], iv = iraw[ix];
        la[t] = l;
        uu[t] = (1.f - l) * (iv * sigmoidf_(iv));
    }
    float hf = 0.f, p = 1.f;
#pragma unroll
    for (int t = 0; t < SCAN_TS; t++) {
        hf = fmaf(la[t], hf, uu[t]); p *= la[t];
        vals[t] = fmaf(cf, p, hf);
    }
    float hb = 0.f, q = 1.f;
#pragma unroll
    for (int t = SCAN_TS - 1; t >= 0; t--) {
        hb = fmaf(la[t], hb, uu[t]); q *= la[t];
        vals[t] += fmaf(cb, q, hb);
    }
    // per-row block sums of squares (2 barriers total)
#pragma unroll
    for (int t = 0; t < SCAN_TS; t++) {
        float ss = vals[t] * vals[t];
#pragma unroll
        for (int o = 16; o > 0; o >>= 1) ss += __shfl_xor_sync(0xffffffffu, ss, o);
        if (lane == 0) red[t][wid] = ss;
    }
    __syncthreads();
    {
        // warp w reduces rows 2w (lanes 0-15) and 2w+1 (lanes 16-31)
        const int row = wid * 2 + (lane >> 4);
        float v = red[row][lane & 15];
#pragma unroll
        for (int o = 8; o > 0; o >>= 1) v += __shfl_xor_sync(0xffffffffu, v, o);
        if ((lane & 15) == 0) tot[row] = v;
    }
    __syncthreads();
#pragma unroll
    for (int t = 0; t < SCAN_TS; t++) {
        const size_t ix = base + (size_t)t * DIM;
        const float scale = rsqrtf(tot[t] * (1.f / DIM) + 1e-6f);
        out[ix] = __float2half_rn(vals[t] * scale * g[ix]);
    }
}

__global__ void ln_add(const float* __restrict__ y, const float* __restrict__ resid,
                       const float* __restrict__ gam, const float* __restrict__ bet,
                       float* __restrict__ out, __half* __restrict__ outH) {
    const int row = blockIdx.x * 8 + (threadIdx.x >> 5), lane = threadIdx.x & 31;
    const float* yr = y + (size_t)row * DIM;
    float4 v[4]; float s1 = 0.f, s2 = 0.f;
#pragma unroll
    for (int i = 0; i < 4; i++) {
        v[i] = *(const float4*)(yr + i * 128 + lane * 4);
        s1 += v[i].x + v[i].y + v[i].z + v[i].w;
        s2 += v[i].x * v[i].x + v[i].y * v[i].y + v[i].z * v[i].z + v[i].w * v[i].w;
    }
#pragma unroll
    for (int o = 16; o > 0; o >>= 1) {
        s1 += __shfl_xor_sync(0xffffffffu, s1, o);
        s2 += __shfl_xor_sync(0xffffffffu, s2, o);
    }
    const float mean = s1 * (1.f / DIM);
    const float inv = rsqrtf(s2 * (1.f / DIM) - mean * mean + 1e-5f);
    const float* rr = resid + (size_t)row * DIM;
    float* outr = out + (size_t)row * DIM;
    __half* outh = outH ? outH + (size_t)row * DIM : nullptr;
#pragma unroll
    for (int i = 0; i < 4; i++) {
        const int col = i * 128 + lane * 4;
        float4 gv = *(const float4*)(gam + col);
        float4 bv = *(const float4*)(bet + col);
        float4 xv = *(const float4*)(rr + col);
        float4 r;
        r.x = xv.x + (v[i].x - mean) * inv * gv.x + bv.x;
        r.y = xv.y + (v[i].y - mean) * inv * gv.y + bv.y;
        r.z = xv.z + (v[i].z - mean) * inv * gv.z + bv.z;
        r.w = xv.w + (v[i].w - mean) * inv * gv.w + bv.w;
        *(float4*)(outr + col) = r;
        if (outh) {
            __half2 a = __floats2half2_rn(r.x, r.y);
            __half2 b = __floats2half2_rn(r.z, r.w);
            uint2 u; u.x = *(uint32_t*)&a; u.y = *(uint32_t*)&b;
            *(uint2*)(outh + col) = u;
        }
    }
}

extern "C" void kernel_launch(void* const* d_in, const int* in_sizes, int n_in,
                              void* d_out, int out_size)
{
    const float* x = (const float*)d_in[0];
    const float* lbp = (const float*)d_in[1];
    const float* Wi = (const float*)d_in[2];  const float* bi = (const float*)d_in[3];
    const float* Wf = (const float*)d_in[4];  const float* bf = (const float*)d_in[5];
    const float* Wg = (const float*)d_in[6];  const float* bg = (const float*)d_in[7];
    const float* Wo = (const float*)d_in[8];  const float* bo = (const float*)d_in[9];
    const float* tn_g = (const float*)d_in[10]; const float* tn_b = (const float*)d_in[11];
    const float* fn_g = (const float*)d_in[12]; const float* fn_b = (const float*)d_in[13];
    const float* W1 = (const float*)d_in[14]; const float* b1 = (const float*)d_in[15];
    const float* W2 = (const float*)d_in[16]; const float* b2 = (const float*)d_in[17];
    const float* W3 = (const float*)d_in[18]; const float* b3 = (const float*)d_in[19];
    float* out = (float*)d_out;

    float *bA, *bB, *bC, *bD, *bE, *bF, *wt;
    cudaGetSymbolAddress((void**)&bA, g_bufA);
    cudaGetSymbolAddress((void**)&bB, g_bufB);
    cudaGetSymbolAddress((void**)&bC, g_bufC);
    cudaGetSymbolAddress((void**)&bD, g_bufD);
    cudaGetSymbolAddress((void**)&bE, g_bufE);
    cudaGetSymbolAddress((void**)&bF, g_bufF);
    cudaGetSymbolAddress((void**)&wt, g_WT);

    __half* wh = (__half*)wt;
    __half* WoT = wh + 786432;
    __half* W1T = wh + 1048576;
    __half* W2T = wh + 1572864;
    __half* W3T = wh + 2097152;
    float* bcat = wt + 1310720;

    __half* xh  = (__half*)bD;     // dead after TRI GEMM
    __half* hgh = (__half*)bD;     // pass3_rms output (xh dead, no aliasing with lam/iraw/g)
    __half* x1h = (__half*)bD;     // written by ln_add after hgh consumed
    __half* ph  = (__half*)bF;

    float* prod  = bE;
    float* lastF = bE + CHN;
    float* lastB = bE + 2 * CHN;
    float* CF = bF;
    float* CB = bF + CHN;

    cudaFuncSetAttribute(tc_gemm<MODE_TRI>,   cudaFuncAttributeMaxDynamicSharedMemorySize, SMEM_BYTES);
    cudaFuncSetAttribute(tc_gemm<MODE_PLAIN>, cudaFuncAttributeMaxDynamicSharedMemorySize, SMEM_BYTES);
    cudaFuncSetAttribute(tc_gemm<MODE_GLU>,   cudaFuncAttributeMaxDynamicSharedMemorySize, SMEM_BYTES);

    dim3 tb(32, 8);
    round_xh<<<32768, 256>>>(x, xh);
    transpose_all<<<2560, tb>>>(Wf, Wi, Wg, Wo, W1, W2, W3, wh);
    bias_cat<<<6, 256>>>(bf, bi, bg, bcat);

    dim3 blk(256);
    dim3 gD(4, 512), gG(8, 512), gTri(12, 512);
    const int rowsBlocks = MROWS / 8;
    const int scanBlocks = BSZ * SCAN_CH;   // 2048

    // lam->bA, iraw->bB, g->bC
    tc_gemm<MODE_TRI><<<gTri, blk, SMEM_BYTES>>>(xh, wh, bcat, bA, bB, bC, nullptr, lbp, DIM, DIM);
    scan_pass1<<<scanBlocks, 512>>>(bA, bB, prod, lastF, lastB);
    scan_pass2<<<(BSZ * DIM + 255) / 256, 256>>>(prod, lastF, lastB, CF, CB);
    scan_pass3_rms<<<scanBlocks, 512>>>(bA, bB, CF, CB, bC, hgh);   // hg(half) -> bD
    tc_gemm<MODE_PLAIN><<<gD, blk, SMEM_BYTES>>>(hgh, WoT, bo, bB, nullptr, nullptr, nullptr, nullptr, DIM, DIM);
    ln_add<<<rowsBlocks, 256>>>(bB, x, tn_g, tn_b, bC, x1h);        // bC = x1, bD = half(x1)
    tc_gemm<MODE_PLAIN><<<gG, blk, SMEM_BYTES>>>(x1h, W2T, b2, bE, nullptr, nullptr, nullptr, nullptr, DGLU, DIM);
    tc_gemm<MODE_GLU><<<gG, blk, SMEM_BYTES>>>(x1h, W1T, b1, ph, nullptr, nullptr, bE, nullptr, DGLU, DIM);
    tc_gemm<MODE_PLAIN><<<gD, blk, SMEM_BYTES>>>(ph, W3T, b3, bB, nullptr, nullptr, nullptr, nullptr, DIM, DGLU);
    ln_add<<<rowsBlocks, 256>>>(bB, bC, fn_g, fn_b, out, nullptr);
}

// round 14
// speedup vs baseline: 1.1699x; 1.1699x over previous
#include <cuda_runtime.h>
#include <cuda_fp16.h>
#include <math.h>
#include <stdint.h>

#define BSZ 32
#define SEQ 2048
#define DIM 512
#define DGLU 1024
#define MROWS (BSZ * SEQ)
#define SCAN_TS 32
#define SCAN_CH (SEQ / SCAN_TS)

#define HROW 72
#define TILEH (128 * HROW)
#define STAGEH (2 * TILEH)
#define NSTAGE 3
#define SMEM_BYTES (NSTAGE * STAGEH * 2)   // 110592

__device__ float g_bufA[(size_t)MROWS * DIM];
__device__ float g_bufB[(size_t)MROWS * DIM];
__device__ float g_bufC[(size_t)MROWS * DIM];
__device__ float g_bufD[(size_t)MROWS * DIM];
__device__ float g_bufE[(size_t)MROWS * DGLU];
__device__ float g_bufF[(size_t)MROWS * DGLU];
__device__ float g_WT[1312768];

__device__ __forceinline__ float sigmoidf_(float v) { return 1.f / (1.f + expf(-v)); }

enum { MODE_PLAIN = 0, MODE_GLU = 1, MODE_TRI = 2 };

__device__ __forceinline__ void mma_f16(float* d, const uint32_t* a, const uint32_t* b) {
    asm volatile("mma.sync.aligned.m16n8k16.row.col.f32.f16.f16.f32 "
                 "{%0,%1,%2,%3}, {%4,%5,%6,%7}, {%8,%9}, {%0,%1,%2,%3};"
                 : "+f"(d[0]), "+f"(d[1]), "+f"(d[2]), "+f"(d[3])
                 : "r"(a[0]), "r"(a[1]), "r"(a[2]), "r"(a[3]), "r"(b[0]), "r"(b[1]));
}
__device__ __forceinline__ void cpasync16(uint32_t dst, const void* src) {
    asm volatile("cp.async.cg.shared.global [%0], [%1], 16;" :: "r"(dst), "l"(src));
}
__device__ __forceinline__ uint32_t smem_u32(const void* p) {
    uint32_t a;
    asm("{ .reg .u64 t; cvta.to.shared.u64 t, %1; cvt.u32.u64 %0, t; }" : "=r"(a) : "l"(p));
    return a;
}

__device__ __forceinline__ void stage_in(uint32_t smem_stage_u, const __half* Ab, const __half* Bb,
                                         int K, int kc, int tid) {
#pragma unroll
    for (int i = 0; i < 8; i++) {
        const int idx = tid + i * 256;
        const int mat = idx >> 10;
        const int r   = (idx >> 3) & 127;
        const int c8  = idx & 7;
        const __half* src = (mat ? Bb : Ab) + (size_t)r * K + kc * 64 + c8 * 8;
        const uint32_t dst = smem_stage_u + (uint32_t)(mat * TILEH + r * HROW + c8 * 8) * 2u;
        cpasync16(dst, src);
    }
}

// C[M,N] = epilogue(A[M,K] @ WT[N,K]^T + bias); BK=64, 3-stage, one barrier/chunk
template <int MODE>
__global__ __launch_bounds__(256)
void tc_gemm(const __half* __restrict__ A, const __half* __restrict__ WT,
             const float* __restrict__ bias, void* __restrict__ Cv,
             float* __restrict__ C1, float* __restrict__ C2,
             const float* __restrict__ aux, const float* __restrict__ lbp, int N, int K)
{
    extern __shared__ __half sm[];

    const int tid = threadIdx.x, wid = tid >> 5, lane = tid & 31;
    const int g = lane >> 2, cc = lane & 3;
    const int bm = blockIdx.y * 128;
    const int wm = (wid >> 2) * 64, wn = (wid & 3) * 32;
    const uint32_t sm_u = smem_u32(sm);

    const __half* Ab = A + (size_t)bm * K;
    const __half* Bb = WT + (size_t)blockIdx.x * 128 * K;
    const int NK = K >> 6;

    float acc[4][4][4];
#pragma unroll
    for (int mf = 0; mf < 4; mf++)
#pragma unroll
        for (int nf = 0; nf < 4; nf++)
#pragma unroll
            for (int k = 0; k < 4; k++) acc[mf][nf][k] = 0.f;

    stage_in(sm_u, Ab, Bb, K, 0, tid);
    asm volatile("cp.async.commit_group;");
    if (NK > 1) {
        stage_in(sm_u + STAGEH * 2, Ab, Bb, K, 1, tid);
        asm volatile("cp.async.commit_group;");
    }

    int sidx = 0;
    for (int kc = 0; kc < NK; kc++) {
        asm volatile("cp.async.wait_group 1;");
        __syncthreads();
        if (kc + 2 < NK) {
            int ps = sidx + 2; if (ps >= NSTAGE) ps -= NSTAGE;
            stage_in(sm_u + ps * STAGEH * 2, Ab, Bb, K, kc + 2, tid);
            asm volatile("cp.async.commit_group;");
        } else {
            asm volatile("cp.async.commit_group;");
        }

        const __half* As = sm + sidx * STAGEH;
        const __half* Bs = As + TILEH;
#pragma unroll
        for (int ks = 0; ks < 4; ks++) {
            uint32_t af[4][4], bf[4][2];
#pragma unroll
            for (int mf = 0; mf < 4; mf++) {
                const __half* p = As + (wm + mf * 16 + g) * HROW + ks * 16 + cc * 2;
                af[mf][0] = *(const uint32_t*)(p);
                af[mf][1] = *(const uint32_t*)(p + 8 * HROW);
                af[mf][2] = *(const uint32_t*)(p + 8);
                af[mf][3] = *(const uint32_t*)(p + 8 * HROW + 8);
            }
#pragma unroll
            for (int nf = 0; nf < 4; nf++) {
                const __half* q = Bs + (wn + nf * 8 + g) * HROW + ks * 16 + cc * 2;
                bf[nf][0] = *(const uint32_t*)(q);
                bf[nf][1] = *(const uint32_t*)(q + 8);
            }
#pragma unroll
            for (int mf = 0; mf < 4; mf++)
#pragma unroll
                for (int nf = 0; nf < 4; nf++)
                    mma_f16(acc[mf][nf], af[mf], bf[nf]);
        }
        if (++sidx == NSTAGE) sidx = 0;
    }

    int seg = 0, bnl = blockIdx.x * 128;
    float* Cout = (float*)Cv;
    float lb = 0.f;
    if (MODE == MODE_TRI) {
        seg = blockIdx.x >> 2;
        bnl = (blockIdx.x & 3) * 128;
        Cout = (seg == 0) ? (float*)Cv : (seg == 1 ? C1 : C2);
        if (seg == 0) lb = __ldg(lbp);
    }

#pragma unroll
    for (int mf = 0; mf < 4; mf++) {
#pragma unroll
        for (int half_ = 0; half_ < 2; half_++) {
            const int row = bm + wm + mf * 16 + g + half_ * 8;
            const float* Arow = (MODE == MODE_GLU) ? aux + (size_t)row * N : nullptr;
#pragma unroll
            for (int nf = 0; nf < 4; nf++) {
                const int col = bnl + wn + nf * 8 + cc * 2;
                const float2 bb = *(const float2*)&bias[blockIdx.x * 128 + wn + nf * 8 + cc * 2];
                float v0 = acc[mf][nf][half_ * 2 + 0] + bb.x;
                float v1 = acc[mf][nf][half_ * 2 + 1] + bb.y;
                float o0 = v0, o1 = v1;
                if (MODE == MODE_TRI) {
                    if (seg == 0) {
                        o0 = lb + (1.f - lb) * sigmoidf_(v0);
                        o1 = lb + (1.f - lb) * sigmoidf_(v1);
                    } else if (seg == 2) {
                        o0 = sigmoidf_(v0); o1 = sigmoidf_(v1);
                    }
                } else if (MODE == MODE_GLU) {
                    const float2 ax = *(const float2*)(Arow + col);
                    o0 = (v0 * sigmoidf_(v0)) * ax.x;
                    o1 = (v1 * sigmoidf_(v1)) * ax.y;
                }
                if (MODE == MODE_GLU) {
                    __half2 h2 = __floats2half2_rn(o0, o1);
                    *(__half2*)((__half*)Cv + (size_t)row * N + col) = h2;
                } else {
                    float2 o; o.x = o0; o.y = o1;
                    *(float2*)(Cout + (size_t)row * N + col) = o;
                }
            }
        }
    }
}

__global__ void transpose_all(const float* __restrict__ s0, const float* __restrict__ s1,
                              const float* __restrict__ s2, const float* __restrict__ s3,
                              const float* __restrict__ s4, const float* __restrict__ s5,
                              const float* __restrict__ s6, __half* __restrict__ wh)
{
    __shared__ float tile[32][33];
    const int bid = blockIdx.x;
    const float* src; __half* dst; int K, N, ti;
    if (bid < 1024) {
        const int j = bid >> 8; ti = bid & 255;
        src = (j == 0) ? s0 : (j == 1) ? s1 : (j == 2) ? s2 : s3;
        dst = wh + (size_t)j * 262144; K = DIM; N = DIM;
    } else if (bid < 2048) {
        const int j = (bid - 1024) >> 9; ti = (bid - 1024) & 511;
        src = j ? s5 : s4;
        dst = wh + 1048576 + (size_t)j * 524288; K = DIM; N = DGLU;
    } else {
        ti = bid - 2048;
        src = s6; dst = wh + 2097152; K = DGLU; N = DIM;
    }
    const int ntx = N >> 5;
    const int n0 = (ti % ntx) * 32, k0 = (ti / ntx) * 32;
    for (int i = threadIdx.y; i < 32; i += 8)
        tile[i][threadIdx.x] = src[(size_t)(k0 + i) * N + n0 + threadIdx.x];
    __syncthreads();
    for (int i = threadIdx.y; i < 32; i += 8)
        dst[(size_t)(n0 + i) * K + k0 + threadIdx.x] = __float2half_rn(tile[threadIdx.x][i]);
}

__global__ void round_xh(const float* __restrict__ src, __half* __restrict__ dst) {
    const size_t i = (size_t)blockIdx.x * blockDim.x + threadIdx.x;
    float4 v = *(const float4*)(src + i * 4);
    __half2 a = __floats2half2_rn(v.x, v.y);
    __half2 b = __floats2half2_rn(v.z, v.w);
    uint2 u; u.x = *(uint32_t*)&a; u.y = *(uint32_t*)&b;
    *(uint2*)(dst + i * 4) = u;
}

__global__ void bias_cat(const float* __restrict__ b0, const float* __restrict__ b1,
                         const float* __restrict__ b2, float* __restrict__ dst) {
    const int i = blockIdx.x * blockDim.x + threadIdx.x;
    if (i < DIM) dst[i] = b0[i];
    else if (i < 2 * DIM) dst[i] = b1[i - DIM];
    else if (i < 3 * DIM) dst[i] = b2[i - 2 * DIM];
}

// pass1: streaming, writes local scans + summaries (round-12 form; no big reg arrays)
__global__ __launch_bounds__(512)
void scan_pass1(const float* __restrict__ lam, const float* __restrict__ iraw,
                float* __restrict__ lF, float* __restrict__ lB,
                float* __restrict__ prod, float* __restrict__ lastF, float* __restrict__ lastB)
{
    const int b = blockIdx.x >> 6, ch = blockIdx.x & 63;
    const int d = threadIdx.x;
    const size_t base = ((size_t)b * SEQ + ch * SCAN_TS) * DIM + d;
    float hf = 0.f, p = 1.f;
#pragma unroll 4
    for (int t = 0; t < SCAN_TS; t++) {
        const size_t ix = base + (size_t)t * DIM;
        const float l = lam[ix], iv = iraw[ix];
        const float u = (1.f - l) * (iv * sigmoidf_(iv));
        hf = fmaf(l, hf, u); p *= l; lF[ix] = hf;
    }
    float hb = 0.f;
#pragma unroll 4
    for (int t = SCAN_TS - 1; t >= 0; t--) {
        const size_t ix = base + (size_t)t * DIM;
        const float l = lam[ix], iv = iraw[ix];
        const float u = (1.f - l) * (iv * sigmoidf_(iv));
        hb = fmaf(l, hb, u); lB[ix] = hb;
    }
    const int ci = (b * SCAN_CH + ch) * DIM + d;
    prod[ci] = p; lastF[ci] = hf; lastB[ci] = hb;
}

__global__ void scan_pass2(const float* __restrict__ prod, const float* __restrict__ lastF,
                           const float* __restrict__ lastB, float* __restrict__ CF, float* __restrict__ CB)
{
    const int c = blockIdx.x * blockDim.x + threadIdx.x;
    if (c >= BSZ * DIM) return;
    const int b = c >> 9, d = c & 511;
    float cf = 0.f;
#pragma unroll 4
    for (int ch = 0; ch < SCAN_CH; ch++) {
        const int i = (b * SCAN_CH + ch) * DIM + d;
        CF[i] = cf; cf = fmaf(prod[i], cf, lastF[i]);
    }
    float cb = 0.f;
#pragma unroll 4
    for (int ch = SCAN_CH - 1; ch >= 0; ch--) {
        const int i = (b * SCAN_CH + ch) * DIM + d;
        CB[i] = cb; cb = fmaf(prod[i], cb, lastB[i]);
    }
}

// pass3 (round-12 streaming form) + fused rmsnorm*gate -> half.
// Registers: vals[32] + few; lam/lF/lB streamed.
__global__ __launch_bounds__(512)
void scan_pass3_rms(const float* __restrict__ lam, const float* __restrict__ lF,
                    const float* __restrict__ lB, const float* __restrict__ CF,
                    const float* __restrict__ CB, const float* __restrict__ g,
                    __half* __restrict__ out)
{
    __shared__ float red[SCAN_TS][17];
    __shared__ float tot[SCAN_TS];
    const int b = blockIdx.x >> 6, ch = blockIdx.x & 63;
    const int d = threadIdx.x, wid = d >> 5, lane = d & 31;
    const size_t base = ((size_t)b * SEQ + ch * SCAN_TS) * DIM + d;
    const int ci = (b * SCAN_CH + ch) * DIM + d;
    const float cf = CF[ci], cb = CB[ci];

    float vals[SCAN_TS];
    float p = 1.f;
#pragma unroll
    for (int t = 0; t < SCAN_TS; t++) {
        const size_t ix = base + (size_t)t * DIM;
        p *= lam[ix];
        vals[t] = fmaf(cf, p, lF[ix]);
    }
    float q = 1.f;
#pragma unroll
    for (int t = SCAN_TS - 1; t >= 0; t--) {
        const size_t ix = base + (size_t)t * DIM;
        q *= lam[ix];
        vals[t] += fmaf(cb, q, lB[ix]);
    }
    // per-row block sums of squares (2 barriers total)
#pragma unroll
    for (int t = 0; t < SCAN_TS; t++) {
        float ss = vals[t] * vals[t];
#pragma unroll
        for (int o = 16; o > 0; o >>= 1) ss += __shfl_xor_sync(0xffffffffu, ss, o);
        if (lane == 0) red[t][wid] = ss;
    }
    __syncthreads();
    {
        const int row = wid * 2 + (lane >> 4);   // warp w -> rows 2w, 2w+1
        float v = red[row][lane & 15];
#pragma unroll
        for (int o = 8; o > 0; o >>= 1) v += __shfl_xor_sync(0xffffffffu, v, o);
        if ((lane & 15) == 0) tot[row] = v;
    }
    __syncthreads();
#pragma unroll
    for (int t = 0; t < SCAN_TS; t++) {
        const size_t ix = base + (size_t)t * DIM;
        const float scale = rsqrtf(tot[t] * (1.f / DIM) + 1e-6f);
        out[ix] = __float2half_rn(vals[t] * scale * g[ix]);
    }
}

__global__ void ln_add(const float* __restrict__ y, const float* __restrict__ resid,
                       const float* __restrict__ gam, const float* __restrict__ bet,
                       float* __restrict__ out, __half* __restrict__ outH) {
    const int row = blockIdx.x * 8 + (threadIdx.x >> 5), lane = threadIdx.x & 31;
    const float* yr = y + (size_t)row * DIM;
    float4 v[4]; float s1 = 0.f, s2 = 0.f;
#pragma unroll
    for (int i = 0; i < 4; i++) {
        v[i] = *(const float4*)(yr + i * 128 + lane * 4);
        s1 += v[i].x + v[i].y + v[i].z + v[i].w;
        s2 += v[i].x * v[i].x + v[i].y * v[i].y + v[i].z * v[i].z + v[i].w * v[i].w;
    }
#pragma unroll
    for (int o = 16; o > 0; o >>= 1) {
        s1 += __shfl_xor_sync(0xffffffffu, s1, o);
        s2 += __shfl_xor_sync(0xffffffffu, s2, o);
    }
    const float mean = s1 * (1.f / DIM);
    const float inv = rsqrtf(s2 * (1.f / DIM) - mean * mean + 1e-5f);
    const float* rr = resid + (size_t)row * DIM;
    float* outr = out + (size_t)row * DIM;
    __half* outh = outH ? outH + (size_t)row * DIM : nullptr;
#pragma unroll
    for (int i = 0; i < 4; i++) {
        const int col = i * 128 + lane * 4;
        float4 gv = *(const float4*)(gam + col);
        float4 bv = *(const float4*)(bet + col);
        float4 xv = *(const float4*)(rr + col);
        float4 r;
        r.x = xv.x + (v[i].x - mean) * inv * gv.x + bv.x;
        r.y = xv.y + (v[i].y - mean) * inv * gv.y + bv.y;
        r.z = xv.z + (v[i].z - mean) * inv * gv.z + bv.z;
        r.w = xv.w + (v[i].w - mean) * inv * gv.w + bv.w;
        *(float4*)(outr + col) = r;
        if (outh) {
            __half2 a = __floats2half2_rn(r.x, r.y);
            __half2 b = __floats2half2_rn(r.z, r.w);
            uint2 u; u.x = *(uint32_t*)&a; u.y = *(uint32_t*)&b;
            *(uint2*)(outh + col) = u;
        }
    }
}

extern "C" void kernel_launch(void* const* d_in, const int* in_sizes, int n_in,
                              void* d_out, int out_size)
{
    const float* x = (const float*)d_in[0];
    const float* lbp = (const float*)d_in[1];
    const float* Wi = (const float*)d_in[2];  const float* bi = (const float*)d_in[3];
    const float* Wf = (const float*)d_in[4];  const float* bf = (const float*)d_in[5];
    const float* Wg = (const float*)d_in[6];  const float* bg = (const float*)d_in[7];
    const float* Wo = (const float*)d_in[8];  const float* bo = (const float*)d_in[9];
    const float* tn_g = (const float*)d_in[10]; const float* tn_b = (const float*)d_in[11];
    const float* fn_g = (const float*)d_in[12]; const float* fn_b = (const float*)d_in[13];
    const float* W1 = (const float*)d_in[14]; const float* b1 = (const float*)d_in[15];
    const float* W2 = (const float*)d_in[16]; const float* b2 = (const float*)d_in[17];
    const float* W3 = (const float*)d_in[18]; const float* b3 = (const float*)d_in[19];
    float* out = (float*)d_out;

    float *bA, *bB, *bC, *bD, *bE, *bF, *wt;
    cudaGetSymbolAddress((void**)&bA, g_bufA);
    cudaGetSymbolAddress((void**)&bB, g_bufB);
    cudaGetSymbolAddress((void**)&bC, g_bufC);
    cudaGetSymbolAddress((void**)&bD, g_bufD);
    cudaGetSymbolAddress((void**)&bE, g_bufE);
    cudaGetSymbolAddress((void**)&bF, g_bufF);
    cudaGetSymbolAddress((void**)&wt, g_WT);

    __half* wh = (__half*)wt;
    __half* WoT = wh + 786432;
    __half* W1T = wh + 1048576;
    __half* W2T = wh + 1572864;
    __half* W3T = wh + 2097152;
    float* bcat = wt + 1310720;

    __half* xh  = (__half*)bD;     // dead after TRI GEMM
    __half* hgh = (__half*)bD;     // pass3_rms output (no alias with lam=bA, lF=bE, lB=bF, g=bC)
    __half* x1h = (__half*)bD;     // written after hgh consumed
    __half* ph  = (__half*)bF;

    float* lF = bE;
    float* lB = bF;
    float* prod  = bE + (size_t)MROWS * DIM;
    float* lastF = prod + (size_t)BSZ * SCAN_CH * DIM;
    float* lastB = lastF + (size_t)BSZ * SCAN_CH * DIM;
    float* CF = bF + (size_t)MROWS * DIM;
    float* CB = CF + (size_t)BSZ * SCAN_CH * DIM;

    cudaFuncSetAttribute(tc_gemm<MODE_TRI>,   cudaFuncAttributeMaxDynamicSharedMemorySize, SMEM_BYTES);
    cudaFuncSetAttribute(tc_gemm<MODE_PLAIN>, cudaFuncAttributeMaxDynamicSharedMemorySize, SMEM_BYTES);
    cudaFuncSetAttribute(tc_gemm<MODE_GLU>,   cudaFuncAttributeMaxDynamicSharedMemorySize, SMEM_BYTES);

    dim3 tb(32, 8);
    round_xh<<<32768, 256>>>(x, xh);
    transpose_all<<<2560, tb>>>(Wf, Wi, Wg, Wo, W1, W2, W3, wh);
    bias_cat<<<6, 256>>>(bf, bi, bg, bcat);

    dim3 blk(256);
    dim3 gD(4, 512), gG(8, 512), gTri(12, 512);
    const int rowsBlocks = MROWS / 8;
    const int scanBlocks = BSZ * SCAN_CH;

    // lam->bA, iraw->bB, g->bC
    tc_gemm<MODE_TRI><<<gTri, blk, SMEM_BYTES>>>(xh, wh, bcat, bA, bB, bC, nullptr, lbp, DIM, DIM);
    scan_pass1<<<scanBlocks, 512>>>(bA, bB, lF, lB, prod, lastF, lastB);
    scan_pass2<<<(BSZ * DIM + 255) / 256, 256>>>(prod, lastF, lastB, CF, CB);
    scan_pass3_rms<<<scanBlocks, 512>>>(bA, lF, lB, CF, CB, bC, hgh);   // hg(half) -> bD
    tc_gemm<MODE_PLAIN><<<gD, blk, SMEM_BYTES>>>(hgh, WoT, bo, bB, nullptr, nullptr, nullptr, nullptr, DIM, DIM);
    ln_add<<<rowsBlocks, 256>>>(bB, x, tn_g, tn_b, bC, x1h);            // bC = x1, bD = half(x1)
    tc_gemm<MODE_PLAIN><<<gG, blk, SMEM_BYTES>>>(x1h, W2T, b2, bE, nullptr, nullptr, nullptr, nullptr, DGLU, DIM);
    tc_gemm<MODE_GLU><<<gG, blk, SMEM_BYTES>>>(x1h, W1T, b1, ph, nullptr, nullptr, bE, nullptr, DGLU, DIM);
    tc_gemm<MODE_PLAIN><<<gD, blk, SMEM_BYTES>>>(ph, W3T, b3, bB, nullptr, nullptr, nullptr, nullptr, DIM, DGLU);
    ln_add<<<rowsBlocks, 256>>>(bB, bC, fn_g, fn_b, out, nullptr);
}

// round 15
// speedup vs baseline: 1.2159x; 1.0394x over previous
#include <cuda_runtime.h>
#include <cuda_fp16.h>
#include <math.h>
#include <stdint.h>

#define BSZ 32
#define SEQ 2048
#define DIM 512
#define DGLU 1024
#define MROWS (BSZ * SEQ)
#define SCAN_TS 32
#define SCAN_CH (SEQ / SCAN_TS)

#define HROW 72
#define TILEH (128 * HROW)
#define STAGEH (2 * TILEH)
#define NSTAGE 3
#define SMEM_BYTES (NSTAGE * STAGEH * 2)   // 110592

__device__ float g_bufA[(size_t)MROWS * DIM];
__device__ float g_bufB[(size_t)MROWS * DIM];
__device__ float g_bufC[(size_t)MROWS * DIM];
__device__ float g_bufD[(size_t)MROWS * DIM];
__device__ float g_bufE[(size_t)MROWS * DGLU];
__device__ float g_bufF[(size_t)MROWS * DGLU];
__device__ float g_WT[1312768];

__device__ __forceinline__ float sigmoidf_(float v) { return 1.f / (1.f + expf(-v)); }

enum { MODE_PLAIN = 0, MODE_GLU = 1, MODE_TRI = 2 };

__device__ __forceinline__ void mma_f16(float* d, const uint32_t* a, const uint32_t* b) {
    asm volatile("mma.sync.aligned.m16n8k16.row.col.f32.f16.f16.f32 "
                 "{%0,%1,%2,%3}, {%4,%5,%6,%7}, {%8,%9}, {%0,%1,%2,%3};"
                 : "+f"(d[0]), "+f"(d[1]), "+f"(d[2]), "+f"(d[3])
                 : "r"(a[0]), "r"(a[1]), "r"(a[2]), "r"(a[3]), "r"(b[0]), "r"(b[1]));
}
#define LDSM4(r0, r1, r2, r3, addr) \
    asm volatile("ldmatrix.sync.aligned.m8n8.x4.shared.b16 {%0,%1,%2,%3}, [%4];" \
                 : "=r"(r0), "=r"(r1), "=r"(r2), "=r"(r3) : "r"(addr))
__device__ __forceinline__ void cpasync16(uint32_t dst, const void* src) {
    asm volatile("cp.async.cg.shared.global [%0], [%1], 16;" :: "r"(dst), "l"(src));
}
__device__ __forceinline__ uint32_t smem_u32(const void* p) {
    uint32_t a;
    asm("{ .reg .u64 t; cvta.to.shared.u64 t, %1; cvt.u32.u64 %0, t; }" : "=r"(a) : "l"(p));
    return a;
}

__device__ __forceinline__ void stage_in(uint32_t smem_stage_u, const __half* Ab, const __half* Bb,
                                         int K, int kc, int tid) {
#pragma unroll
    for (int i = 0; i < 8; i++) {
        const int idx = tid + i * 256;
        const int mat = idx >> 10;
        const int r   = (idx >> 3) & 127;
        const int c8  = idx & 7;
        const __half* src = (mat ? Bb : Ab) + (size_t)r * K + kc * 64 + c8 * 8;
        const uint32_t dst = smem_stage_u + (uint32_t)(mat * TILEH + r * HROW + c8 * 8) * 2u;
        cpasync16(dst, src);
    }
}

// C[M,N] = epilogue(A[M,K] @ WT[N,K]^T + bias); BK=64, 3-stage, one barrier/chunk,
// fragments via ldmatrix.x4
template <int MODE>
__global__ __launch_bounds__(256)
void tc_gemm(const __half* __restrict__ A, const __half* __restrict__ WT,
             const float* __restrict__ bias, void* __restrict__ Cv,
             float* __restrict__ C1, float* __restrict__ C2,
             const float* __restrict__ aux, const float* __restrict__ lbp, int N, int K)
{
    extern __shared__ __half sm[];

    const int tid = threadIdx.x, wid = tid >> 5, lane = tid & 31;
    const int g = lane >> 2, cc = lane & 3;
    const int bm = blockIdx.y * 128;
    const int wm = (wid >> 2) * 64, wn = (wid & 3) * 32;
    const uint32_t sm_u = smem_u32(sm);

    // ldmatrix per-lane byte offsets (within a stage)
    const int arow = ((lane >> 3) & 1) * 8 + (lane & 7);  // m row within 16
    const int akoff = (lane >> 4) * 8;                    // k half-offset 0/8
    uint32_t aoff[4];
#pragma unroll
    for (int mf = 0; mf < 4; mf++)
        aoff[mf] = (uint32_t)((wm + mf * 16 + arow) * HROW + akoff) * 2u;
    uint32_t boff[2];
#pragma unroll
    for (int j = 0; j < 2; j++)
        boff[j] = (uint32_t)((wn + (j * 2 + (lane >> 4)) * 8 + (lane & 7)) * HROW
                             + ((lane >> 3) & 1) * 8) * 2u + (uint32_t)TILEH * 2u;

    const __half* Ab = A + (size_t)bm * K;
    const __half* Bb = WT + (size_t)blockIdx.x * 128 * K;
    const int NK = K >> 6;

    float acc[4][4][4];
#pragma unroll
    for (int mf = 0; mf < 4; mf++)
#pragma unroll
        for (int nf = 0; nf < 4; nf++)
#pragma unroll
            for (int k = 0; k < 4; k++) acc[mf][nf][k] = 0.f;

    stage_in(sm_u, Ab, Bb, K, 0, tid);
    asm volatile("cp.async.commit_group;");
    if (NK > 1) {
        stage_in(sm_u + STAGEH * 2, Ab, Bb, K, 1, tid);
        asm volatile("cp.async.commit_group;");
    }

    int sidx = 0;
    for (int kc = 0; kc < NK; kc++) {
        asm volatile("cp.async.wait_group 1;");
        __syncthreads();
        if (kc + 2 < NK) {
            int ps = sidx + 2; if (ps >= NSTAGE) ps -= NSTAGE;
            stage_in(sm_u + ps * STAGEH * 2, Ab, Bb, K, kc + 2, tid);
            asm volatile("cp.async.commit_group;");
        } else {
            asm volatile("cp.async.commit_group;");
        }

        const uint32_t stg = sm_u + sidx * STAGEH * 2;
#pragma unroll
        for (int ks = 0; ks < 4; ks++) {
            uint32_t af[4][4], bf[4][2];
#pragma unroll
            for (int mf = 0; mf < 4; mf++)
                LDSM4(af[mf][0], af[mf][1], af[mf][2], af[mf][3], stg + aoff[mf] + ks * 32);
            LDSM4(bf[0][0], bf[0][1], bf[1][0], bf[1][1], stg + boff[0] + ks * 32);
            LDSM4(bf[2][0], bf[2][1], bf[3][0], bf[3][1], stg + boff[1] + ks * 32);
#pragma unroll
            for (int mf = 0; mf < 4; mf++)
#pragma unroll
                for (int nf = 0; nf < 4; nf++)
                    mma_f16(acc[mf][nf], af[mf], bf[nf]);
        }
        if (++sidx == NSTAGE) sidx = 0;
    }

    int seg = 0, bnl = blockIdx.x * 128;
    float* Cout = (float*)Cv;
    float lb = 0.f;
    if (MODE == MODE_TRI) {
        seg = blockIdx.x >> 2;
        bnl = (blockIdx.x & 3) * 128;
        Cout = (seg == 0) ? (float*)Cv : (seg == 1 ? C1 : C2);
        if (seg == 0) lb = __ldg(lbp);
    }

#pragma unroll
    for (int mf = 0; mf < 4; mf++) {
#pragma unroll
        for (int half_ = 0; half_ < 2; half_++) {
            const int row = bm + wm + mf * 16 + g + half_ * 8;
            const float* Arow = (MODE == MODE_GLU) ? aux + (size_t)row * N : nullptr;
#pragma unroll
            for (int nf = 0; nf < 4; nf++) {
                const int col = bnl + wn + nf * 8 + cc * 2;
                const float2 bb = *(const float2*)&bias[blockIdx.x * 128 + wn + nf * 8 + cc * 2];
                float v0 = acc[mf][nf][half_ * 2 + 0] + bb.x;
                float v1 = acc[mf][nf][half_ * 2 + 1] + bb.y;
                float o0 = v0, o1 = v1;
                if (MODE == MODE_TRI) {
                    if (seg == 0) {
                        o0 = lb + (1.f - lb) * sigmoidf_(v0);
                        o1 = lb + (1.f - lb) * sigmoidf_(v1);
                    } else if (seg == 2) {
                        o0 = sigmoidf_(v0); o1 = sigmoidf_(v1);
                    }
                } else if (MODE == MODE_GLU) {
                    const float2 ax = *(const float2*)(Arow + col);
                    o0 = (v0 * sigmoidf_(v0)) * ax.x;
                    o1 = (v1 * sigmoidf_(v1)) * ax.y;
                }
                if (MODE == MODE_GLU) {
                    __half2 h2 = __floats2half2_rn(o0, o1);
                    *(__half2*)((__half*)Cv + (size_t)row * N + col) = h2;
                } else {
                    float2 o; o.x = o0; o.y = o1;
                    *(float2*)(Cout + (size_t)row * N + col) = o;
                }
            }
        }
    }
}

__global__ void transpose_all(const float* __restrict__ s0, const float* __restrict__ s1,
                              const float* __restrict__ s2, const float* __restrict__ s3,
                              const float* __restrict__ s4, const float* __restrict__ s5,
                              const float* __restrict__ s6, __half* __restrict__ wh)
{
    __shared__ float tile[32][33];
    const int bid = blockIdx.x;
    const float* src; __half* dst; int K, N, ti;
    if (bid < 1024) {
        const int j = bid >> 8; ti = bid & 255;
        src = (j == 0) ? s0 : (j == 1) ? s1 : (j == 2) ? s2 : s3;
        dst = wh + (size_t)j * 262144; K = DIM; N = DIM;
    } else if (bid < 2048) {
        const int j = (bid - 1024) >> 9; ti = (bid - 1024) & 511;
        src = j ? s5 : s4;
        dst = wh + 1048576 + (size_t)j * 524288; K = DIM; N = DGLU;
    } else {
        ti = bid - 2048;
        src = s6; dst = wh + 2097152; K = DGLU; N = DIM;
    }
    const int ntx = N >> 5;
    const int n0 = (ti % ntx) * 32, k0 = (ti / ntx) * 32;
    for (int i = threadIdx.y; i < 32; i += 8)
        tile[i][threadIdx.x] = src[(size_t)(k0 + i) * N + n0 + threadIdx.x];
    __syncthreads();
    for (int i = threadIdx.y; i < 32; i += 8)
        dst[(size_t)(n0 + i) * K + k0 + threadIdx.x] = __float2half_rn(tile[threadIdx.x][i]);
}

__global__ void round_xh(const float* __restrict__ src, __half* __restrict__ dst) {
    const size_t i = (size_t)blockIdx.x * blockDim.x + threadIdx.x;
    float4 v = *(const float4*)(src + i * 4);
    __half2 a = __floats2half2_rn(v.x, v.y);
    __half2 b = __floats2half2_rn(v.z, v.w);
    uint2 u; u.x = *(uint32_t*)&a; u.y = *(uint32_t*)&b;
    *(uint2*)(dst + i * 4) = u;
}

__global__ void bias_cat(const float* __restrict__ b0, const float* __restrict__ b1,
                         const float* __restrict__ b2, float* __restrict__ dst) {
    const int i = blockIdx.x * blockDim.x + threadIdx.x;
    if (i < DIM) dst[i] = b0[i];
    else if (i < 2 * DIM) dst[i] = b1[i - DIM];
    else if (i < 3 * DIM) dst[i] = b2[i - 2 * DIM];
}

__global__ __launch_bounds__(512)
void scan_pass1(const float* __restrict__ lam, const float* __restrict__ iraw,
                float* __restrict__ lF, float* __restrict__ lB,
                float* __restrict__ prod, float* __restrict__ lastF, float* __restrict__ lastB)
{
    const int b = blockIdx.x >> 6, ch = blockIdx.x & 63;
    const int d = threadIdx.x;
    const size_t base = ((size_t)b * SEQ + ch * SCAN_TS) * DIM + d;
    float hf = 0.f, p = 1.f;
#pragma unroll 4
    for (int t = 0; t < SCAN_TS; t++) {
        const size_t ix = base + (size_t)t * DIM;
        const float l = lam[ix], iv = iraw[ix];
        const float u = (1.f - l) * (iv * sigmoidf_(iv));
        hf = fmaf(l, hf, u); p *= l; lF[ix] = hf;
    }
    float hb = 0.f;
#pragma unroll 4
    for (int t = SCAN_TS - 1; t >= 0; t--) {
        const size_t ix = base + (size_t)t * DIM;
        const float l = lam[ix], iv = iraw[ix];
        const float u = (1.f - l) * (iv * sigmoidf_(iv));
        hb = fmaf(l, hb, u); lB[ix] = hb;
    }
    const int ci = (b * SCAN_CH + ch) * DIM + d;
    prod[ci] = p; lastF[ci] = hf; lastB[ci] = hb;
}

__global__ void scan_pass2(const float* __restrict__ prod, const float* __restrict__ lastF,
                           const float* __restrict__ lastB, float* __restrict__ CF, float* __restrict__ CB)
{
    const int c = blockIdx.x * blockDim.x + threadIdx.x;
    if (c >= BSZ * DIM) return;
    const int b = c >> 9, d = c & 511;
    float cf = 0.f;
#pragma unroll 4
    for (int ch = 0; ch < SCAN_CH; ch++) {
        const int i = (b * SCAN_CH + ch) * DIM + d;
        CF[i] = cf; cf = fmaf(prod[i], cf, lastF[i]);
    }
    float cb = 0.f;
#pragma unroll 4
    for (int ch = SCAN_CH - 1; ch >= 0; ch--) {
        const int i = (b * SCAN_CH + ch) * DIM + d;
        CB[i] = cb; cb = fmaf(prod[i], cb, lastB[i]);
    }
}

__global__ __launch_bounds__(512)
void scan_pass3_rms(const float* __restrict__ lam, const float* __restrict__ lF,
                    const float* __restrict__ lB, const float* __restrict__ CF,
                    const float* __restrict__ CB, const float* __restrict__ g,
                    __half* __restrict__ out)
{
    __shared__ float red[SCAN_TS][17];
    __shared__ float tot[SCAN_TS];
    const int b = blockIdx.x >> 6, ch = blockIdx.x & 63;
    const int d = threadIdx.x, wid = d >> 5, lane = d & 31;
    const size_t base = ((size_t)b * SEQ + ch * SCAN_TS) * DIM + d;
    const int ci = (b * SCAN_CH + ch) * DIM + d;
    const float cf = CF[ci], cb = CB[ci];

    float vals[SCAN_TS];
    float p = 1.f;
#pragma unroll
    for (int t = 0; t < SCAN_TS; t++) {
        const size_t ix = base + (size_t)t * DIM;
        p *= lam[ix];
        vals[t] = fmaf(cf, p, lF[ix]);
    }
    float q = 1.f;
#pragma unroll
    for (int t = SCAN_TS - 1; t >= 0; t--) {
        const size_t ix = base + (size_t)t * DIM;
        q *= lam[ix];
        vals[t] += fmaf(cb, q, lB[ix]);
    }
#pragma unroll
    for (int t = 0; t < SCAN_TS; t++) {
        float ss = vals[t] * vals[t];
#pragma unroll
        for (int o = 16; o > 0; o >>= 1) ss += __shfl_xor_sync(0xffffffffu, ss, o);
        if (lane == 0) red[t][wid] = ss;
    }
    __syncthreads();
    {
        const int row = wid * 2 + (lane >> 4);
        float v = red[row][lane & 15];
#pragma unroll
        for (int o = 8; o > 0; o >>= 1) v += __shfl_xor_sync(0xffffffffu, v, o);
        if ((lane & 15) == 0) tot[row] = v;
    }
    __syncthreads();
#pragma unroll
    for (int t = 0; t < SCAN_TS; t++) {
        const size_t ix = base + (size_t)t * DIM;
        const float scale = rsqrtf(tot[t] * (1.f / DIM) + 1e-6f);
        out[ix] = __float2half_rn(vals[t] * scale * g[ix]);
    }
}

__global__ void ln_add(const float* __restrict__ y, const float* __restrict__ resid,
                       const float* __restrict__ gam, const float* __restrict__ bet,
                       float* __restrict__ out, __half* __restrict__ outH) {
    const int row = blockIdx.x * 8 + (threadIdx.x >> 5), lane = threadIdx.x & 31;
    const float* yr = y + (size_t)row * DIM;
    float4 v[4]; float s1 = 0.f, s2 = 0.f;
#pragma unroll
    for (int i = 0; i < 4; i++) {
        v[i] = *(const float4*)(yr + i * 128 + lane * 4);
        s1 += v[i].x + v[i].y + v[i].z + v[i].w;
        s2 += v[i].x * v[i].x + v[i].y * v[i].y + v[i].z * v[i].z + v[i].w * v[i].w;
    }
#pragma unroll
    for (int o = 16; o > 0; o >>= 1) {
        s1 += __shfl_xor_sync(0xffffffffu, s1, o);
        s2 += __shfl_xor_sync(0xffffffffu, s2, o);
    }
    const float mean = s1 * (1.f / DIM);
    const float inv = rsqrtf(s2 * (1.f / DIM) - mean * mean + 1e-5f);
    const float* rr = resid + (size_t)row * DIM;
    float* outr = out + (size_t)row * DIM;
    __half* outh = outH ? outH + (size_t)row * DIM : nullptr;
#pragma unroll
    for (int i = 0; i < 4; i++) {
        const int col = i * 128 + lane * 4;
        float4 gv = *(const float4*)(gam + col);
        float4 bv = *(const float4*)(bet + col);
        float4 xv = *(const float4*)(rr + col);
        float4 r;
        r.x = xv.x + (v[i].x - mean) * inv * gv.x + bv.x;
        r.y = xv.y + (v[i].y - mean) * inv * gv.y + bv.y;
        r.z = xv.z + (v[i].z - mean) * inv * gv.z + bv.z;
        r.w = xv.w + (v[i].w - mean) * inv * gv.w + bv.w;
        *(float4*)(outr + col) = r;
        if (outh) {
            __half2 a = __floats2half2_rn(r.x, r.y);
            __half2 b = __floats2half2_rn(r.z, r.w);
            uint2 u; u.x = *(uint32_t*)&a; u.y = *(uint32_t*)&b;
            *(uint2*)(outh + col) = u;
        }
    }
}

extern "C" void kernel_launch(void* const* d_in, const int* in_sizes, int n_in,
                              void* d_out, int out_size)
{
    const float* x = (const float*)d_in[0];
    const float* lbp = (const float*)d_in[1];
    const float* Wi = (const float*)d_in[2];  const float* bi = (const float*)d_in[3];
    const float* Wf = (const float*)d_in[4];  const float* bf = (const float*)d_in[5];
    const float* Wg = (const float*)d_in[6];  const float* bg = (const float*)d_in[7];
    const float* Wo = (const float*)d_in[8];  const float* bo = (const float*)d_in[9];
    const float* tn_g = (const float*)d_in[10]; const float* tn_b = (const float*)d_in[11];
    const float* fn_g = (const float*)d_in[12]; const float* fn_b = (const float*)d_in[13];
    const float* W1 = (const float*)d_in[14]; const float* b1 = (const float*)d_in[15];
    const float* W2 = (const float*)d_in[16]; const float* b2 = (const float*)d_in[17];
    const float* W3 = (const float*)d_in[18]; const float* b3 = (const float*)d_in[19];
    float* out = (float*)d_out;

    float *bA, *bB, *bC, *bD, *bE, *bF, *wt;
    cudaGetSymbolAddress((void**)&bA, g_bufA);
    cudaGetSymbolAddress((void**)&bB, g_bufB);
    cudaGetSymbolAddress((void**)&bC, g_bufC);
    cudaGetSymbolAddress((void**)&bD, g_bufD);
    cudaGetSymbolAddress((void**)&bE, g_bufE);
    cudaGetSymbolAddress((void**)&bF, g_bufF);
    cudaGetSymbolAddress((void**)&wt, g_WT);

    __half* wh = (__half*)wt;
    __half* WoT = wh + 786432;
    __half* W1T = wh + 1048576;
    __half* W2T = wh + 1572864;
    __half* W3T = wh + 2097152;
    float* bcat = wt + 1310720;

    __half* xh  = (__half*)bD;
    __half* hgh = (__half*)bD;
    __half* x1h = (__half*)bD;
    __half* ph  = (__half*)bF;

    float* lF = bE;
    float* lB = bF;
    float* prod  = bE + (size_t)MROWS * DIM;
    float* lastF = prod + (size_t)BSZ * SCAN_CH * DIM;
    float* lastB = lastF + (size_t)BSZ * SCAN_CH * DIM;
    float* CF = bF + (size_t)MROWS * DIM;
    float* CB = CF + (size_t)BSZ * SCAN_CH * DIM;

    cudaFuncSetAttribute(tc_gemm<MODE_TRI>,   cudaFuncAttributeMaxDynamicSharedMemorySize, SMEM_BYTES);
    cudaFuncSetAttribute(tc_gemm<MODE_PLAIN>, cudaFuncAttributeMaxDynamicSharedMemorySize, SMEM_BYTES);
    cudaFuncSetAttribute(tc_gemm<MODE_GLU>,   cudaFuncAttributeMaxDynamicSharedMemorySize, SMEM_BYTES);

    dim3 tb(32, 8);
    round_xh<<<32768, 256>>>(x, xh);
    transpose_all<<<2560, tb>>>(Wf, Wi, Wg, Wo, W1, W2, W3, wh);
    bias_cat<<<6, 256>>>(bf, bi, bg, bcat);

    dim3 blk(256);
    dim3 gD(4, 512), gG(8, 512), gTri(12, 512);
    const int rowsBlocks = MROWS / 8;
    const int scanBlocks = BSZ * SCAN_CH;

    tc_gemm<MODE_TRI><<<gTri, blk, SMEM_BYTES>>>(xh, wh, bcat, bA, bB, bC, nullptr, lbp, DIM, DIM);
    scan_pass1<<<scanBlocks, 512>>>(bA, bB, lF, lB, prod, lastF, lastB);
    scan_pass2<<<(BSZ * DIM + 255) / 256, 256>>>(prod, lastF, lastB, CF, CB);
    scan_pass3_rms<<<scanBlocks, 512>>>(bA, lF, lB, CF, CB, bC, hgh);
    tc_gemm<MODE_PLAIN><<<gD, blk, SMEM_BYTES>>>(hgh, WoT, bo, bB, nullptr, nullptr, nullptr, nullptr, DIM, DIM);
    ln_add<<<rowsBlocks, 256>>>(bB, x, tn_g, tn_b, bC, x1h);
    tc_gemm<MODE_PLAIN><<<gG, blk, SMEM_BYTES>>>(x1h, W2T, b2, bE, nullptr, nullptr, nullptr, nullptr, DGLU, DIM);
    tc_gemm<MODE_GLU><<<gG, blk, SMEM_BYTES>>>(x1h, W1T, b1, ph, nullptr, nullptr, bE, nullptr, DGLU, DIM);
    tc_gemm<MODE_PLAIN><<<gD, blk, SMEM_BYTES>>>(ph, W3T, b3, bB, nullptr, nullptr, nullptr, nullptr, DIM, DGLU);
    ln_add<<<rowsBlocks, 256>>>(bB, bC, fn_g, fn_b, out, nullptr);
}

// round 16
// speedup vs baseline: 1.2303x; 1.0118x over previous
#include <cuda_runtime.h>
#include <cuda_fp16.h>
#include <math.h>
#include <stdint.h>

#define BSZ 32
#define SEQ 2048
#define DIM 512
#define DGLU 1024
#define MROWS (BSZ * SEQ)
#define SCAN_TS 32
#define SCAN_CH (SEQ / SCAN_TS)

#define HROW 72
#define TILEH (128 * HROW)
#define STAGEH (2 * TILEH)
#define NSTAGE 3
#define SMEM_BYTES (NSTAGE * STAGEH * 2)   // 110592

__device__ float g_bufA[(size_t)MROWS * DIM];
__device__ float g_bufB[(size_t)MROWS * DIM];
__device__ float g_bufC[(size_t)MROWS * DIM];
__device__ float g_bufD[(size_t)MROWS * DIM];
__device__ float g_bufE[(size_t)MROWS * DGLU];
__device__ float g_bufF[(size_t)MROWS * DGLU];
__device__ float g_WT[1312768];

__device__ __forceinline__ float sigmoidf_(float v) { return 1.f / (1.f + expf(-v)); }

enum { MODE_PLAIN = 0, MODE_GLU = 1, MODE_TRI = 2 };

__device__ __forceinline__ void mma_f16(float* d, const uint32_t* a, const uint32_t* b) {
    asm volatile("mma.sync.aligned.m16n8k16.row.col.f32.f16.f16.f32 "
                 "{%0,%1,%2,%3}, {%4,%5,%6,%7}, {%8,%9}, {%0,%1,%2,%3};"
                 : "+f"(d[0]), "+f"(d[1]), "+f"(d[2]), "+f"(d[3])
                 : "r"(a[0]), "r"(a[1]), "r"(a[2]), "r"(a[3]), "r"(b[0]), "r"(b[1]));
}
#define LDSM4(r0, r1, r2, r3, addr) \
    asm volatile("ldmatrix.sync.aligned.m8n8.x4.shared.b16 {%0,%1,%2,%3}, [%4];" \
                 : "=r"(r0), "=r"(r1), "=r"(r2), "=r"(r3) : "r"(addr))
__device__ __forceinline__ void cpasync16(uint32_t dst, const void* src) {
    asm volatile("cp.async.cg.shared.global [%0], [%1], 16;" :: "r"(dst), "l"(src));
}
__device__ __forceinline__ uint32_t smem_u32(const void* p) {
    uint32_t a;
    asm("{ .reg .u64 t; cvta.to.shared.u64 t, %1; cvt.u32.u64 %0, t; }" : "=r"(a) : "l"(p));
    return a;
}

__device__ __forceinline__ void stage_in(uint32_t smem_stage_u, const __half* Ab, const __half* Bb,
                                         int K, int kc, int tid) {
#pragma unroll
    for (int i = 0; i < 8; i++) {
        const int idx = tid + i * 256;
        const int mat = idx >> 10;
        const int r   = (idx >> 3) & 127;
        const int c8  = idx & 7;
        const __half* src = (mat ? Bb : Ab) + (size_t)r * K + kc * 64 + c8 * 8;
        const uint32_t dst = smem_stage_u + (uint32_t)(mat * TILEH + r * HROW + c8 * 8) * 2u;
        cpasync16(dst, src);
    }
}

// C[M,N] = epilogue(A[M,K] @ WT[N,K]^T + bias); BK=64, 3-stage, one barrier/chunk,
// fragments via ldmatrix.x4
template <int MODE>
__global__ __launch_bounds__(256)
void tc_gemm(const __half* __restrict__ A, const __half* __restrict__ WT,
             const float* __restrict__ bias, void* __restrict__ Cv,
             float* __restrict__ C1, float* __restrict__ C2,
             const float* __restrict__ aux, const float* __restrict__ lbp, int N, int K)
{
    extern __shared__ __half sm[];

    const int tid = threadIdx.x, wid = tid >> 5, lane = tid & 31;
    const int g = lane >> 2, cc = lane & 3;
    const int bm = blockIdx.y * 128;
    const int wm = (wid >> 2) * 64, wn = (wid & 3) * 32;
    const uint32_t sm_u = smem_u32(sm);

    const int arow = ((lane >> 3) & 1) * 8 + (lane & 7);
    const int akoff = (lane >> 4) * 8;
    uint32_t aoff[4];
#pragma unroll
    for (int mf = 0; mf < 4; mf++)
        aoff[mf] = (uint32_t)((wm + mf * 16 + arow) * HROW + akoff) * 2u;
    uint32_t boff[2];
#pragma unroll
    for (int j = 0; j < 2; j++)
        boff[j] = (uint32_t)((wn + (j * 2 + (lane >> 4)) * 8 + (lane & 7)) * HROW
                             + ((lane >> 3) & 1) * 8) * 2u + (uint32_t)TILEH * 2u;

    const __half* Ab = A + (size_t)bm * K;
    const __half* Bb = WT + (size_t)blockIdx.x * 128 * K;
    const int NK = K >> 6;

    float acc[4][4][4];
#pragma unroll
    for (int mf = 0; mf < 4; mf++)
#pragma unroll
        for (int nf = 0; nf < 4; nf++)
#pragma unroll
            for (int k = 0; k < 4; k++) acc[mf][nf][k] = 0.f;

    stage_in(sm_u, Ab, Bb, K, 0, tid);
    asm volatile("cp.async.commit_group;");
    if (NK > 1) {
        stage_in(sm_u + STAGEH * 2, Ab, Bb, K, 1, tid);
        asm volatile("cp.async.commit_group;");
    }

    int sidx = 0;
    for (int kc = 0; kc < NK; kc++) {
        asm volatile("cp.async.wait_group 1;");
        __syncthreads();
        if (kc + 2 < NK) {
            int ps = sidx + 2; if (ps >= NSTAGE) ps -= NSTAGE;
            stage_in(sm_u + ps * STAGEH * 2, Ab, Bb, K, kc + 2, tid);
            asm volatile("cp.async.commit_group;");
        } else {
            asm volatile("cp.async.commit_group;");
        }

        const uint32_t stg = sm_u + sidx * STAGEH * 2;
#pragma unroll
        for (int ks = 0; ks < 4; ks++) {
            uint32_t af[4][4], bf[4][2];
#pragma unroll
            for (int mf = 0; mf < 4; mf++)
                LDSM4(af[mf][0], af[mf][1], af[mf][2], af[mf][3], stg + aoff[mf] + ks * 32);
            LDSM4(bf[0][0], bf[0][1], bf[1][0], bf[1][1], stg + boff[0] + ks * 32);
            LDSM4(bf[2][0], bf[2][1], bf[3][0], bf[3][1], stg + boff[1] + ks * 32);
#pragma unroll
            for (int mf = 0; mf < 4; mf++)
#pragma unroll
                for (int nf = 0; nf < 4; nf++)
                    mma_f16(acc[mf][nf], af[mf], bf[nf]);
        }
        if (++sidx == NSTAGE) sidx = 0;
    }

    int seg = 0, bnl = blockIdx.x * 128;
    float* Cout = (float*)Cv;
    float lb = 0.f;
    if (MODE == MODE_TRI) {
        seg = blockIdx.x >> 2;
        bnl = (blockIdx.x & 3) * 128;
        Cout = (seg == 0) ? (float*)Cv : (seg == 1 ? C1 : C2);
        if (seg == 0) lb = __ldg(lbp);
    }

#pragma unroll
    for (int mf = 0; mf < 4; mf++) {
#pragma unroll
        for (int half_ = 0; half_ < 2; half_++) {
            const int row = bm + wm + mf * 16 + g + half_ * 8;
            const float* Arow = (MODE == MODE_GLU) ? aux + (size_t)row * N : nullptr;
#pragma unroll
            for (int nf = 0; nf < 4; nf++) {
                const int col = bnl + wn + nf * 8 + cc * 2;
                const float2 bb = *(const float2*)&bias[blockIdx.x * 128 + wn + nf * 8 + cc * 2];
                float v0 = acc[mf][nf][half_ * 2 + 0] + bb.x;
                float v1 = acc[mf][nf][half_ * 2 + 1] + bb.y;
                float o0 = v0, o1 = v1;
                if (MODE == MODE_TRI) {
                    if (seg == 0) {
                        o0 = lb + (1.f - lb) * sigmoidf_(v0);
                        o1 = lb + (1.f - lb) * sigmoidf_(v1);
                    } else if (seg == 2) {
                        o0 = sigmoidf_(v0); o1 = sigmoidf_(v1);
                    }
                } else if (MODE == MODE_GLU) {
                    const float2 ax = *(const float2*)(Arow + col);
                    o0 = (v0 * sigmoidf_(v0)) * ax.x;
                    o1 = (v1 * sigmoidf_(v1)) * ax.y;
                }
                if (MODE == MODE_GLU) {
                    __half2 h2 = __floats2half2_rn(o0, o1);
                    *(__half2*)((__half*)Cv + (size_t)row * N + col) = h2;
                } else {
                    float2 o; o.x = o0; o.y = o1;
                    *(float2*)(Cout + (size_t)row * N + col) = o;
                }
            }
        }
    }
}

__global__ void transpose_all(const float* __restrict__ s0, const float* __restrict__ s1,
                              const float* __restrict__ s2, const float* __restrict__ s3,
                              const float* __restrict__ s4, const float* __restrict__ s5,
                              const float* __restrict__ s6, __half* __restrict__ wh)
{
    __shared__ float tile[32][33];
    const int bid = blockIdx.x;
    const float* src; __half* dst; int K, N, ti;
    if (bid < 1024) {
        const int j = bid >> 8; ti = bid & 255;
        src = (j == 0) ? s0 : (j == 1) ? s1 : (j == 2) ? s2 : s3;
        dst = wh + (size_t)j * 262144; K = DIM; N = DIM;
    } else if (bid < 2048) {
        const int j = (bid - 1024) >> 9; ti = (bid - 1024) & 511;
        src = j ? s5 : s4;
        dst = wh + 1048576 + (size_t)j * 524288; K = DIM; N = DGLU;
    } else {
        ti = bid - 2048;
        src = s6; dst = wh + 2097152; K = DGLU; N = DIM;
    }
    const int ntx = N >> 5;
    const int n0 = (ti % ntx) * 32, k0 = (ti / ntx) * 32;
    for (int i = threadIdx.y; i < 32; i += 8)
        tile[i][threadIdx.x] = src[(size_t)(k0 + i) * N + n0 + threadIdx.x];
    __syncthreads();
    for (int i = threadIdx.y; i < 32; i += 8)
        dst[(size_t)(n0 + i) * K + k0 + threadIdx.x] = __float2half_rn(tile[threadIdx.x][i]);
}

__global__ void round_xh(const float* __restrict__ src, __half* __restrict__ dst) {
    const size_t i = (size_t)blockIdx.x * blockDim.x + threadIdx.x;
    float4 v = *(const float4*)(src + i * 4);
    __half2 a = __floats2half2_rn(v.x, v.y);
    __half2 b = __floats2half2_rn(v.z, v.w);
    uint2 u; u.x = *(uint32_t*)&a; u.y = *(uint32_t*)&b;
    *(uint2*)(dst + i * 4) = u;
}

__global__ void bias_cat(const float* __restrict__ b0, const float* __restrict__ b1,
                         const float* __restrict__ b2, float* __restrict__ dst) {
    const int i = blockIdx.x * blockDim.x + threadIdx.x;
    if (i < DIM) dst[i] = b0[i];
    else if (i < 2 * DIM) dst[i] = b1[i - DIM];
    else if (i < 3 * DIM) dst[i] = b2[i - 2 * DIM];
}

// pass1: streaming; local scans stored as fp16
__global__ __launch_bounds__(512)
void scan_pass1(const float* __restrict__ lam, const float* __restrict__ iraw,
                __half* __restrict__ lF, __half* __restrict__ lB,
                float* __restrict__ prod, float* __restrict__ lastF, float* __restrict__ lastB)
{
    const int b = blockIdx.x >> 6, ch = blockIdx.x & 63;
    const int d = threadIdx.x;
    const size_t base = ((size_t)b * SEQ + ch * SCAN_TS) * DIM + d;
    float hf = 0.f, p = 1.f;
#pragma unroll 4
    for (int t = 0; t < SCAN_TS; t++) {
        const size_t ix = base + (size_t)t * DIM;
        const float l = lam[ix], iv = iraw[ix];
        const float u = (1.f - l) * (iv * sigmoidf_(iv));
        hf = fmaf(l, hf, u); p *= l; lF[ix] = __float2half_rn(hf);
    }
    float hb = 0.f;
#pragma unroll 4
    for (int t = SCAN_TS - 1; t >= 0; t--) {
        const size_t ix = base + (size_t)t * DIM;
        const float l = lam[ix], iv = iraw[ix];
        const float u = (1.f - l) * (iv * sigmoidf_(iv));
        hb = fmaf(l, hb, u); lB[ix] = __float2half_rn(hb);
    }
    const int ci = (b * SCAN_CH + ch) * DIM + d;
    prod[ci] = p; lastF[ci] = hf; lastB[ci] = hb;   // summaries stay fp32 (exact carries)
}

__global__ void scan_pass2(const float* __restrict__ prod, const float* __restrict__ lastF,
                           const float* __restrict__ lastB, float* __restrict__ CF, float* __restrict__ CB)
{
    const int c = blockIdx.x * blockDim.x + threadIdx.x;
    if (c >= BSZ * DIM) return;
    const int b = c >> 9, d = c & 511;
    float cf = 0.f;
#pragma unroll 4
    for (int ch = 0; ch < SCAN_CH; ch++) {
        const int i = (b * SCAN_CH + ch) * DIM + d;
        CF[i] = cf; cf = fmaf(prod[i], cf, lastF[i]);
    }
    float cb = 0.f;
#pragma unroll 4
    for (int ch = SCAN_CH - 1; ch >= 0; ch--) {
        const int i = (b * SCAN_CH + ch) * DIM + d;
        CB[i] = cb; cb = fmaf(prod[i], cb, lastB[i]);
    }
}

// pass3 streaming + fused rmsnorm*gate -> half; lF/lB read as fp16
__global__ __launch_bounds__(512)
void scan_pass3_rms(const float* __restrict__ lam, const __half* __restrict__ lF,
                    const __half* __restrict__ lB, const float* __restrict__ CF,
                    const float* __restrict__ CB, const float* __restrict__ g,
                    __half* __restrict__ out)
{
    __shared__ float red[SCAN_TS][17];
    __shared__ float tot[SCAN_TS];
    const int b = blockIdx.x >> 6, ch = blockIdx.x & 63;
    const int d = threadIdx.x, wid = d >> 5, lane = d & 31;
    const size_t base = ((size_t)b * SEQ + ch * SCAN_TS) * DIM + d;
    const int ci = (b * SCAN_CH + ch) * DIM + d;
    const float cf = CF[ci], cb = CB[ci];

    float vals[SCAN_TS];
    float p = 1.f;
#pragma unroll
    for (int t = 0; t < SCAN_TS; t++) {
        const size_t ix = base + (size_t)t * DIM;
        p *= lam[ix];
        vals[t] = fmaf(cf, p, __half2float(lF[ix]));
    }
    float q = 1.f;
#pragma unroll
    for (int t = SCAN_TS - 1; t >= 0; t--) {
        const size_t ix = base + (size_t)t * DIM;
        q *= lam[ix];
        vals[t] += fmaf(cb, q, __half2float(lB[ix]));
    }
#pragma unroll
    for (int t = 0; t < SCAN_TS; t++) {
        float ss = vals[t] * vals[t];
#pragma unroll
        for (int o = 16; o > 0; o >>= 1) ss += __shfl_xor_sync(0xffffffffu, ss, o);
        if (lane == 0) red[t][wid] = ss;
    }
    __syncthreads();
    {
        const int row = wid * 2 + (lane >> 4);
        float v = red[row][lane & 15];
#pragma unroll
        for (int o = 8; o > 0; o >>= 1) v += __shfl_xor_sync(0xffffffffu, v, o);
        if ((lane & 15) == 0) tot[row] = v;
    }
    __syncthreads();
#pragma unroll
    for (int t = 0; t < SCAN_TS; t++) {
        const size_t ix = base + (size_t)t * DIM;
        const float scale = rsqrtf(tot[t] * (1.f / DIM) + 1e-6f);
        out[ix] = __float2half_rn(vals[t] * scale * g[ix]);
    }
}

__global__ void ln_add(const float* __restrict__ y, const float* __restrict__ resid,
                       const float* __restrict__ gam, const float* __restrict__ bet,
                       float* __restrict__ out, __half* __restrict__ outH) {
    const int row = blockIdx.x * 8 + (threadIdx.x >> 5), lane = threadIdx.x & 31;
    const float* yr = y + (size_t)row * DIM;
    float4 v[4]; float s1 = 0.f, s2 = 0.f;
#pragma unroll
    for (int i = 0; i < 4; i++) {
        v[i] = *(const float4*)(yr + i * 128 + lane * 4);
        s1 += v[i].x + v[i].y + v[i].z + v[i].w;
        s2 += v[i].x * v[i].x + v[i].y * v[i].y + v[i].z * v[i].z + v[i].w * v[i].w;
    }
#pragma unroll
    for (int o = 16; o > 0; o >>= 1) {
        s1 += __shfl_xor_sync(0xffffffffu, s1, o);
        s2 += __shfl_xor_sync(0xffffffffu, s2, o);
    }
    const float mean = s1 * (1.f / DIM);
    const float inv = rsqrtf(s2 * (1.f / DIM) - mean * mean + 1e-5f);
    const float* rr = resid + (size_t)row * DIM;
    float* outr = out + (size_t)row * DIM;
    __half* outh = outH ? outH + (size_t)row * DIM : nullptr;
#pragma unroll
    for (int i = 0; i < 4; i++) {
        const int col = i * 128 + lane * 4;
        float4 gv = *(const float4*)(gam + col);
        float4 bv = *(const float4*)(bet + col);
        float4 xv = *(const float4*)(rr + col);
        float4 r;
        r.x = xv.x + (v[i].x - mean) * inv * gv.x + bv.x;
        r.y = xv.y + (v[i].y - mean) * inv * gv.y + bv.y;
        r.z = xv.z + (v[i].z - mean) * inv * gv.z + bv.z;
        r.w = xv.w + (v[i].w - mean) * inv * gv.w + bv.w;
        *(float4*)(outr + col) = r;
        if (outh) {
            __half2 a = __floats2half2_rn(r.x, r.y);
            __half2 b = __floats2half2_rn(r.z, r.w);
            uint2 u; u.x = *(uint32_t*)&a; u.y = *(uint32_t*)&b;
            *(uint2*)(outh + col) = u;
        }
    }
}

extern "C" void kernel_launch(void* const* d_in, const int* in_sizes, int n_in,
                              void* d_out, int out_size)
{
    const float* x = (const float*)d_in[0];
    const float* lbp = (const float*)d_in[1];
    const float* Wi = (const float*)d_in[2];  const float* bi = (const float*)d_in[3];
    const float* Wf = (const float*)d_in[4];  const float* bf = (const float*)d_in[5];
    const float* Wg = (const float*)d_in[6];  const float* bg = (const float*)d_in[7];
    const float* Wo = (const float*)d_in[8];  const float* bo = (const float*)d_in[9];
    const float* tn_g = (const float*)d_in[10]; const float* tn_b = (const float*)d_in[11];
    const float* fn_g = (const float*)d_in[12]; const float* fn_b = (const float*)d_in[13];
    const float* W1 = (const float*)d_in[14]; const float* b1 = (const float*)d_in[15];
    const float* W2 = (const float*)d_in[16]; const float* b2 = (const float*)d_in[17];
    const float* W3 = (const float*)d_in[18]; const float* b3 = (const float*)d_in[19];
    float* out = (float*)d_out;

    float *bA, *bB, *bC, *bD, *bE, *bF, *wt;
    cudaGetSymbolAddress((void**)&bA, g_bufA);
    cudaGetSymbolAddress((void**)&bB, g_bufB);
    cudaGetSymbolAddress((void**)&bC, g_bufC);
    cudaGetSymbolAddress((void**)&bD, g_bufD);
    cudaGetSymbolAddress((void**)&bE, g_bufE);
    cudaGetSymbolAddress((void**)&bF, g_bufF);
    cudaGetSymbolAddress((void**)&wt, g_WT);

    __half* wh = (__half*)wt;
    __half* WoT = wh + 786432;
    __half* W1T = wh + 1048576;
    __half* W2T = wh + 1572864;
    __half* W3T = wh + 2097152;
    float* bcat = wt + 1310720;

    __half* xh  = (__half*)bD;
    __half* hgh = (__half*)bD;
    __half* x1h = (__half*)bD;
    __half* ph  = (__half*)bF;

    // scan scratch in bE: lF(half 33.5M) | lB(half 33.5M) | prod/lastF/lastB (fp32)
    __half* lFh = (__half*)bE;
    __half* lBh = (__half*)bE + (size_t)MROWS * DIM;
    float* prod  = bE + (size_t)MROWS * DIM;        // floats, after 67MB of halves = MROWS*DIM floats
    float* lastF = prod + (size_t)BSZ * SCAN_CH * DIM;
    float* lastB = lastF + (size_t)BSZ * SCAN_CH * DIM;
    float* CF = bF;
    float* CB = bF + (size_t)BSZ * SCAN_CH * DIM;

    cudaFuncSetAttribute(tc_gemm<MODE_TRI>,   cudaFuncAttributeMaxDynamicSharedMemorySize, SMEM_BYTES);
    cudaFuncSetAttribute(tc_gemm<MODE_PLAIN>, cudaFuncAttributeMaxDynamicSharedMemorySize, SMEM_BYTES);
    cudaFuncSetAttribute(tc_gemm<MODE_GLU>,   cudaFuncAttributeMaxDynamicSharedMemorySize, SMEM_BYTES);

    dim3 tb(32, 8);
    round_xh<<<32768, 256>>>(x, xh);
    transpose_all<<<2560, tb>>>(Wf, Wi, Wg, Wo, W1, W2, W3, wh);
    bias_cat<<<6, 256>>>(bf, bi, bg, bcat);

    dim3 blk(256);
    dim3 gD(4, 512), gG(8, 512), gTri(12, 512);
    const int rowsBlocks = MROWS / 8;
    const int scanBlocks = BSZ * SCAN_CH;

    tc_gemm<MODE_TRI><<<gTri, blk, SMEM_BYTES>>>(xh, wh, bcat, bA, bB, bC, nullptr, lbp, DIM, DIM);
    scan_pass1<<<scanBlocks, 512>>>(bA, bB, lFh, lBh, prod, lastF, lastB);
    scan_pass2<<<(BSZ * DIM + 255) / 256, 256>>>(prod, lastF, lastB, CF, CB);
    scan_pass3_rms<<<scanBlocks, 512>>>(bA, lFh, lBh, CF, CB, bC, hgh);
    tc_gemm<MODE_PLAIN><<<gD, blk, SMEM_BYTES>>>(hgh, WoT, bo, bB, nullptr, nullptr, nullptr, nullptr, DIM, DIM);
    ln_add<<<rowsBlocks, 256>>>(bB, x, tn_g, tn_b, bC, x1h);
    tc_gemm<MODE_PLAIN><<<gG, blk, SMEM_BYTES>>>(x1h, W2T, b2, bE, nullptr, nullptr, nullptr, nullptr, DGLU, DIM);
    tc_gemm<MODE_GLU><<<gG, blk, SMEM_BYTES>>>(x1h, W1T, b1, ph, nullptr, nullptr, bE, nullptr, DGLU, DIM);
    tc_gemm<MODE_PLAIN><<<gD, blk, SMEM_BYTES>>>(ph, W3T, b3, bB, nullptr, nullptr, nullptr, nullptr, DIM, DGLU);
    ln_add<<<rowsBlocks, 256>>>(bB, bC, fn_g, fn_b, out, nullptr);
}

// round 17
// speedup vs baseline: 1.3220x; 1.0745x over previous
#include <cuda_runtime.h>
#include <cuda_fp16.h>
#include <math.h>
#include <stdint.h>

#define BSZ 32
#define SEQ 2048
#define DIM 512
#define DGLU 1024
#define MROWS (BSZ * SEQ)
#define SCAN_TS 32
#define SCAN_CH (SEQ / SCAN_TS)

#define HROW 72
#define TILEH (128 * HROW)
#define STAGEH (2 * TILEH)
#define NSTAGE 3
#define SMEM_BYTES (NSTAGE * STAGEH * 2)   // 110592

__device__ float g_bufA[(size_t)MROWS * DIM];
__device__ float g_bufB[(size_t)MROWS * DIM];
__device__ float g_bufC[(size_t)MROWS * DIM];
__device__ float g_bufD[(size_t)MROWS * DIM];
__device__ float g_bufE[(size_t)MROWS * DGLU];
__device__ float g_bufF[(size_t)MROWS * DGLU];
__device__ float g_WT[1312768];

__device__ __forceinline__ float sigmoidf_(float v) { return 1.f / (1.f + expf(-v)); }

enum { MODE_PLAIN = 0, MODE_GLU2 = 1, MODE_TRI = 2 };

__device__ __forceinline__ void mma_f16(float* d, const uint32_t* a, const uint32_t* b) {
    asm volatile("mma.sync.aligned.m16n8k16.row.col.f32.f16.f16.f32 "
                 "{%0,%1,%2,%3}, {%4,%5,%6,%7}, {%8,%9}, {%0,%1,%2,%3};"
                 : "+f"(d[0]), "+f"(d[1]), "+f"(d[2]), "+f"(d[3])
                 : "r"(a[0]), "r"(a[1]), "r"(a[2]), "r"(a[3]), "r"(b[0]), "r"(b[1]));
}
#define LDSM4(r0, r1, r2, r3, addr) \
    asm volatile("ldmatrix.sync.aligned.m8n8.x4.shared.b16 {%0,%1,%2,%3}, [%4];" \
                 : "=r"(r0), "=r"(r1), "=r"(r2), "=r"(r3) : "r"(addr))
__device__ __forceinline__ void cpasync16(uint32_t dst, const void* src) {
    asm volatile("cp.async.cg.shared.global [%0], [%1], 16;" :: "r"(dst), "l"(src));
}
__device__ __forceinline__ uint32_t smem_u32(const void* p) {
    uint32_t a;
    asm("{ .reg .u64 t; cvta.to.shared.u64 t, %1; cvt.u32.u64 %0, t; }" : "=r"(a) : "l"(p));
    return a;
}

__device__ __forceinline__ void stage_in(uint32_t smem_stage_u, const __half* Ab, const __half* Bb,
                                         int K, int kc, int tid) {
#pragma unroll
    for (int i = 0; i < 8; i++) {
        const int idx = tid + i * 256;
        const int mat = idx >> 10;
        const int r   = (idx >> 3) & 127;
        const int c8  = idx & 7;
        const __half* src = (mat ? Bb : Ab) + (size_t)r * K + kc * 64 + c8 * 8;
        const uint32_t dst = smem_stage_u + (uint32_t)(mat * TILEH + r * HROW + c8 * 8) * 2u;
        cpasync16(dst, src);
    }
}

// C[M,N] = epilogue(A[M,K] @ WT[N,K]^T + bias); BK=64, 3-stage, one barrier/chunk,
// fragments via ldmatrix.x4.
// MODE_GLU2: WT is interleaved [W1|W2] (8-row granularity); computes silu(xW1+b1)*(xW2+b2)
//            directly (bias=b1, aux=b2); output half, width N (=DGLU), 64 GLU cols per CTA.
template <int MODE>
__global__ __launch_bounds__(256)
void tc_gemm(const __half* __restrict__ A, const __half* __restrict__ WT,
             const float* __restrict__ bias, void* __restrict__ Cv,
             float* __restrict__ C1, float* __restrict__ C2,
             const float* __restrict__ aux, const float* __restrict__ lbp, int N, int K)
{
    extern __shared__ __half sm[];

    const int tid = threadIdx.x, wid = tid >> 5, lane = tid & 31;
    const int g = lane >> 2, cc = lane & 3;
    const int bm = blockIdx.y * 128;
    const int wm = (wid >> 2) * 64, wn = (wid & 3) * 32;
    const uint32_t sm_u = smem_u32(sm);

    const int arow = ((lane >> 3) & 1) * 8 + (lane & 7);
    const int akoff = (lane >> 4) * 8;
    uint32_t aoff[4];
#pragma unroll
    for (int mf = 0; mf < 4; mf++)
        aoff[mf] = (uint32_t)((wm + mf * 16 + arow) * HROW + akoff) * 2u;
    uint32_t boff[2];
#pragma unroll
    for (int j = 0; j < 2; j++)
        boff[j] = (uint32_t)((wn + (j * 2 + (lane >> 4)) * 8 + (lane & 7)) * HROW
                             + ((lane >> 3) & 1) * 8) * 2u + (uint32_t)TILEH * 2u;

    const __half* Ab = A + (size_t)bm * K;
    const __half* Bb = WT + (size_t)blockIdx.x * 128 * K;
    const int NK = K >> 6;

    float acc[4][4][4];
#pragma unroll
    for (int mf = 0; mf < 4; mf++)
#pragma unroll
        for (int nf = 0; nf < 4; nf++)
#pragma unroll
            for (int k = 0; k < 4; k++) acc[mf][nf][k] = 0.f;

    stage_in(sm_u, Ab, Bb, K, 0, tid);
    asm volatile("cp.async.commit_group;");
    if (NK > 1) {
        stage_in(sm_u + STAGEH * 2, Ab, Bb, K, 1, tid);
        asm volatile("cp.async.commit_group;");
    }

    int sidx = 0;
    for (int kc = 0; kc < NK; kc++) {
        asm volatile("cp.async.wait_group 1;");
        __syncthreads();
        if (kc + 2 < NK) {
            int ps = sidx + 2; if (ps >= NSTAGE) ps -= NSTAGE;
            stage_in(sm_u + ps * STAGEH * 2, Ab, Bb, K, kc + 2, tid);
            asm volatile("cp.async.commit_group;");
        } else {
            asm volatile("cp.async.commit_group;");
        }

        const uint32_t stg = sm_u + sidx * STAGEH * 2;
#pragma unroll
        for (int ks = 0; ks < 4; ks++) {
            uint32_t af[4][4], bf[4][2];
#pragma unroll
            for (int mf = 0; mf < 4; mf++)
                LDSM4(af[mf][0], af[mf][1], af[mf][2], af[mf][3], stg + aoff[mf] + ks * 32);
            LDSM4(bf[0][0], bf[0][1], bf[1][0], bf[1][1], stg + boff[0] + ks * 32);
            LDSM4(bf[2][0], bf[2][1], bf[3][0], bf[3][1], stg + boff[1] + ks * 32);
#pragma unroll
            for (int mf = 0; mf < 4; mf++)
#pragma unroll
                for (int nf = 0; nf < 4; nf++)
                    mma_f16(acc[mf][nf], af[mf], bf[nf]);
        }
        if (++sidx == NSTAGE) sidx = 0;
    }

    if (MODE == MODE_GLU2) {
        // warp covers GLU cols gbase..gbase+15 (nfp 0/1 pairs W1/W2 fragments)
        const int gbase = blockIdx.x * 64 + (wn >> 1);
#pragma unroll
        for (int mf = 0; mf < 4; mf++) {
#pragma unroll
            for (int half_ = 0; half_ < 2; half_++) {
                const int row = bm + wm + mf * 16 + g + half_ * 8;
#pragma unroll
                for (int nfp = 0; nfp < 2; nfp++) {
                    const int gcol = gbase + nfp * 8 + cc * 2;
                    const float2 b1v = *(const float2*)&bias[gcol];
                    const float2 b2v = *(const float2*)&aux[gcol];
                    const float v10 = acc[mf][2 * nfp][half_ * 2 + 0] + b1v.x;
                    const float v11 = acc[mf][2 * nfp][half_ * 2 + 1] + b1v.y;
                    const float v20 = acc[mf][2 * nfp + 1][half_ * 2 + 0] + b2v.x;
                    const float v21 = acc[mf][2 * nfp + 1][half_ * 2 + 1] + b2v.y;
                    const float o0 = (v10 * sigmoidf_(v10)) * v20;
                    const float o1 = (v11 * sigmoidf_(v11)) * v21;
                    __half2 h2 = __floats2half2_rn(o0, o1);
                    *(__half2*)((__half*)Cv + (size_t)row * N + gcol) = h2;
                }
            }
        }
        return;
    }

    int seg = 0, bnl = blockIdx.x * 128;
    float* Cout = (float*)Cv;
    float lb = 0.f;
    if (MODE == MODE_TRI) {
        seg = blockIdx.x >> 2;
        bnl = (blockIdx.x & 3) * 128;
        Cout = (seg == 0) ? (float*)Cv : (seg == 1 ? C1 : C2);
        if (seg == 0) lb = __ldg(lbp);
    }

#pragma unroll
    for (int mf = 0; mf < 4; mf++) {
#pragma unroll
        for (int half_ = 0; half_ < 2; half_++) {
            const int row = bm + wm + mf * 16 + g + half_ * 8;
#pragma unroll
            for (int nf = 0; nf < 4; nf++) {
                const int col = bnl + wn + nf * 8 + cc * 2;
                const float2 bb = *(const float2*)&bias[blockIdx.x * 128 + wn + nf * 8 + cc * 2];
                float v0 = acc[mf][nf][half_ * 2 + 0] + bb.x;
                float v1 = acc[mf][nf][half_ * 2 + 1] + bb.y;
                float o0 = v0, o1 = v1;
                if (MODE == MODE_TRI) {
                    if (seg == 0) {
                        o0 = lb + (1.f - lb) * sigmoidf_(v0);
                        o1 = lb + (1.f - lb) * sigmoidf_(v1);
                    } else if (seg == 2) {
                        o0 = sigmoidf_(v0); o1 = sigmoidf_(v1);
                    }
                }
                float2 o; o.x = o0; o.y = o1;
                *(float2*)(Cout + (size_t)row * N + col) = o;
            }
        }
    }
}

// transposes all weights; W1/W2 interleaved at 8-col granularity into one [2048,512] panel
__global__ void transpose_all(const float* __restrict__ s0, const float* __restrict__ s1,
                              const float* __restrict__ s2, const float* __restrict__ s3,
                              const float* __restrict__ s4, const float* __restrict__ s5,
                              const float* __restrict__ s6, __half* __restrict__ wh)
{
    __shared__ float tile[32][33];
    const int bid = blockIdx.x;
    const float* src; __half* dst; int K, N, ti;
    int glu = 0;   // 0: plain, 1: W1 rows, 2: W2 rows
    if (bid < 1024) {
        const int j = bid >> 8; ti = bid & 255;
        src = (j == 0) ? s0 : (j == 1) ? s1 : (j == 2) ? s2 : s3;
        dst = wh + (size_t)j * 262144; K = DIM; N = DIM;
    } else if (bid < 2048) {
        const int j = (bid - 1024) >> 9; ti = (bid - 1024) & 511;
        src = j ? s5 : s4;
        dst = wh + 1048576;            // interleaved W12 panel
        K = DIM; N = DGLU;
        glu = j ? 2 : 1;
    } else {
        ti = bid - 2048;
        src = s6; dst = wh + 2097152; K = DGLU; N = DIM;
    }
    const int ntx = N >> 5;
    const int n0 = (ti % ntx) * 32, k0 = (ti / ntx) * 32;
    for (int i = threadIdx.y; i < 32; i += 8)
        tile[i][threadIdx.x] = src[(size_t)(k0 + i) * N + n0 + threadIdx.x];
    __syncthreads();
    for (int i = threadIdx.y; i < 32; i += 8) {
        const int n = n0 + i;
        int rowIdx = n;
        if (glu) rowIdx = ((n >> 3) << 4) + (n & 7) + ((glu == 2) ? 8 : 0);
        dst[(size_t)rowIdx * K + k0 + threadIdx.x] = __float2half_rn(tile[threadIdx.x][i]);
    }
}

__global__ void round_xh(const float* __restrict__ src, __half* __restrict__ dst) {
    const size_t i = (size_t)blockIdx.x * blockDim.x + threadIdx.x;
    float4 v = *(const float4*)(src + i * 4);
    __half2 a = __floats2half2_rn(v.x, v.y);
    __half2 b = __floats2half2_rn(v.z, v.w);
    uint2 u; u.x = *(uint32_t*)&a; u.y = *(uint32_t*)&b;
    *(uint2*)(dst + i * 4) = u;
}

__global__ void bias_cat(const float* __restrict__ b0, const float* __restrict__ b1,
                         const float* __restrict__ b2, float* __restrict__ dst) {
    const int i = blockIdx.x * blockDim.x + threadIdx.x;
    if (i < DIM) dst[i] = b0[i];
    else if (i < 2 * DIM) dst[i] = b1[i - DIM];
    else if (i < 3 * DIM) dst[i] = b2[i - 2 * DIM];
}

__global__ __launch_bounds__(512)
void scan_pass1(const float* __restrict__ lam, const float* __restrict__ iraw,
                __half* __restrict__ lF, __half* __restrict__ lB,
                float* __restrict__ prod, float* __restrict__ lastF, float* __restrict__ lastB)
{
    const int b = blockIdx.x >> 6, ch = blockIdx.x & 63;
    const int d = threadIdx.x;
    const size_t base = ((size_t)b * SEQ + ch * SCAN_TS) * DIM + d;
    float hf = 0.f, p = 1.f;
#pragma unroll 4
    for (int t = 0; t < SCAN_TS; t++) {
        const size_t ix = base + (size_t)t * DIM;
        const float l = lam[ix], iv = iraw[ix];
        const float u = (1.f - l) * (iv * sigmoidf_(iv));
        hf = fmaf(l, hf, u); p *= l; lF[ix] = __float2half_rn(hf);
    }
    float hb = 0.f;
#pragma unroll 4
    for (int t = SCAN_TS - 1; t >= 0; t--) {
        const size_t ix = base + (size_t)t * DIM;
        const float l = lam[ix], iv = iraw[ix];
        const float u = (1.f - l) * (iv * sigmoidf_(iv));
        hb = fmaf(l, hb, u); lB[ix] = __float2half_rn(hb);
    }
    const int ci = (b * SCAN_CH + ch) * DIM + d;
    prod[ci] = p; lastF[ci] = hf; lastB[ci] = hb;
}

__global__ void scan_pass2(const float* __restrict__ prod, const float* __restrict__ lastF,
                           const float* __restrict__ lastB, float* __restrict__ CF, float* __restrict__ CB)
{
    const int c = blockIdx.x * blockDim.x + threadIdx.x;
    if (c >= BSZ * DIM) return;
    const int b = c >> 9, d = c & 511;
    float cf = 0.f;
#pragma unroll 4
    for (int ch = 0; ch < SCAN_CH; ch++) {
        const int i = (b * SCAN_CH + ch) * DIM + d;
        CF[i] = cf; cf = fmaf(prod[i], cf, lastF[i]);
    }
    float cb = 0.f;
#pragma unroll 4
    for (int ch = SCAN_CH - 1; ch >= 0; ch--) {
        const int i = (b * SCAN_CH + ch) * DIM + d;
        CB[i] = cb; cb = fmaf(prod[i], cb, lastB[i]);
    }
}

__global__ __launch_bounds__(512)
void scan_pass3_rms(const float* __restrict__ lam, const __half* __restrict__ lF,
                    const __half* __restrict__ lB, const float* __restrict__ CF,
                    const float* __restrict__ CB, const float* __restrict__ g,
                    __half* __restrict__ out)
{
    __shared__ float red[SCAN_TS][17];
    __shared__ float tot[SCAN_TS];
    const int b = blockIdx.x >> 6, ch = blockIdx.x & 63;
    const int d = threadIdx.x, wid = d >> 5, lane = d & 31;
    const size_t base = ((size_t)b * SEQ + ch * SCAN_TS) * DIM + d;
    const int ci = (b * SCAN_CH + ch) * DIM + d;
    const float cf = CF[ci], cb = CB[ci];

    float vals[SCAN_TS];
    float p = 1.f;
#pragma unroll
    for (int t = 0; t < SCAN_TS; t++) {
        const size_t ix = base + (size_t)t * DIM;
        p *= lam[ix];
        vals[t] = fmaf(cf, p, __half2float(lF[ix]));
    }
    float q = 1.f;
#pragma unroll
    for (int t = SCAN_TS - 1; t >= 0; t--) {
        const size_t ix = base + (size_t)t * DIM;
        q *= lam[ix];
        vals[t] += fmaf(cb, q, __half2float(lB[ix]));
    }
#pragma unroll
    for (int t = 0; t < SCAN_TS; t++) {
        float ss = vals[t] * vals[t];
#pragma unroll
        for (int o = 16; o > 0; o >>= 1) ss += __shfl_xor_sync(0xffffffffu, ss, o);
        if (lane == 0) red[t][wid] = ss;
    }
    __syncthreads();
    {
        const int row = wid * 2 + (lane >> 4);
        float v = red[row][lane & 15];
#pragma unroll
        for (int o = 8; o > 0; o >>= 1) v += __shfl_xor_sync(0xffffffffu, v, o);
        if ((lane & 15) == 0) tot[row] = v;
    }
    __syncthreads();
#pragma unroll
    for (int t = 0; t < SCAN_TS; t++) {
        const size_t ix = base + (size_t)t * DIM;
        const float scale = rsqrtf(tot[t] * (1.f / DIM) + 1e-6f);
        out[ix] = __float2half_rn(vals[t] * scale * g[ix]);
    }
}

__global__ void ln_add(const float* __restrict__ y, const float* __restrict__ resid,
                       const float* __restrict__ gam, const float* __restrict__ bet,
                       float* __restrict__ out, __half* __restrict__ outH) {
    const int row = blockIdx.x * 8 + (threadIdx.x >> 5), lane = threadIdx.x & 31;
    const float* yr = y + (size_t)row * DIM;
    float4 v[4]; float s1 = 0.f, s2 = 0.f;
#pragma unroll
    for (int i = 0; i < 4; i++) {
        v[i] = *(const float4*)(yr + i * 128 + lane * 4);
        s1 += v[i].x + v[i].y + v[i].z + v[i].w;
        s2 += v[i].x * v[i].x + v[i].y * v[i].y + v[i].z * v[i].z + v[i].w * v[i].w;
    }
#pragma unroll
    for (int o = 16; o > 0; o >>= 1) {
        s1 += __shfl_xor_sync(0xffffffffu, s1, o);
        s2 += __shfl_xor_sync(0xffffffffu, s2, o);
    }
    const float mean = s1 * (1.f / DIM);
    const float inv = rsqrtf(s2 * (1.f / DIM) - mean * mean + 1e-5f);
    const float* rr = resid + (size_t)row * DIM;
    float* outr = out + (size_t)row * DIM;
    __half* outh = outH ? outH + (size_t)row * DIM : nullptr;
#pragma unroll
    for (int i = 0; i < 4; i++) {
        const int col = i * 128 + lane * 4;
        float4 gv = *(const float4*)(gam + col);
        float4 bv = *(const float4*)(bet + col);
        float4 xv = *(const float4*)(rr + col);
        float4 r;
        r.x = xv.x + (v[i].x - mean) * inv * gv.x + bv.x;
        r.y = xv.y + (v[i].y - mean) * inv * gv.y + bv.y;
        r.z = xv.z + (v[i].z - mean) * inv * gv.z + bv.z;
        r.w = xv.w + (v[i].w - mean) * inv * gv.w + bv.w;
        *(float4*)(outr + col) = r;
        if (outh) {
            __half2 a = __floats2half2_rn(r.x, r.y);
            __half2 b = __floats2half2_rn(r.z, r.w);
            uint2 u; u.x = *(uint32_t*)&a; u.y = *(uint32_t*)&b;
            *(uint2*)(outh + col) = u;
        }
    }
}

extern "C" void kernel_launch(void* const* d_in, const int* in_sizes, int n_in,
                              void* d_out, int out_size)
{
    const float* x = (const float*)d_in[0];
    const float* lbp = (const float*)d_in[1];
    const float* Wi = (const float*)d_in[2];  const float* bi = (const float*)d_in[3];
    const float* Wf = (const float*)d_in[4];  const float* bf = (const float*)d_in[5];
    const float* Wg = (const float*)d_in[6];  const float* bg = (const float*)d_in[7];
    const float* Wo = (const float*)d_in[8];  const float* bo = (const float*)d_in[9];
    const float* tn_g = (const float*)d_in[10]; const float* tn_b = (const float*)d_in[11];
    const float* fn_g = (const float*)d_in[12]; const float* fn_b = (const float*)d_in[13];
    const float* W1 = (const float*)d_in[14]; const float* b1 = (const float*)d_in[15];
    const float* W2 = (const float*)d_in[16]; const float* b2 = (const float*)d_in[17];
    const float* W3 = (const float*)d_in[18]; const float* b3 = (const float*)d_in[19];
    float* out = (float*)d_out;

    float *bA, *bB, *bC, *bD, *bE, *bF, *wt;
    cudaGetSymbolAddress((void**)&bA, g_bufA);
    cudaGetSymbolAddress((void**)&bB, g_bufB);
    cudaGetSymbolAddress((void**)&bC, g_bufC);
    cudaGetSymbolAddress((void**)&bD, g_bufD);
    cudaGetSymbolAddress((void**)&bE, g_bufE);
    cudaGetSymbolAddress((void**)&bF, g_bufF);
    cudaGetSymbolAddress((void**)&wt, g_WT);

    __half* wh = (__half*)wt;
    __half* WoT  = wh + 786432;
    __half* W12T = wh + 1048576;   // interleaved [W1|W2], 2048 x 512
    __half* W3T  = wh + 2097152;
    float* bcat = wt + 1310720;

    __half* xh  = (__half*)bD;
    __half* hgh = (__half*)bD;
    __half* x1h = (__half*)bD;
    __half* ph  = (__half*)bF;

    __half* lFh = (__half*)bE;
    __half* lBh = (__half*)bE + (size_t)MROWS * DIM;
    float* prod  = bE + (size_t)MROWS * DIM;
    float* lastF = prod + (size_t)BSZ * SCAN_CH * DIM;
    float* lastB = lastF + (size_t)BSZ * SCAN_CH * DIM;
    float* CF = bF;
    float* CB = bF + (size_t)BSZ * SCAN_CH * DIM;

    cudaFuncSetAttribute(tc_gemm<MODE_TRI>,   cudaFuncAttributeMaxDynamicSharedMemorySize, SMEM_BYTES);
    cudaFuncSetAttribute(tc_gemm<MODE_PLAIN>, cudaFuncAttributeMaxDynamicSharedMemorySize, SMEM_BYTES);
    cudaFuncSetAttribute(tc_gemm<MODE_GLU2>,  cudaFuncAttributeMaxDynamicSharedMemorySize, SMEM_BYTES);

    dim3 tb(32, 8);
    round_xh<<<32768, 256>>>(x, xh);
    transpose_all<<<2560, tb>>>(Wf, Wi, Wg, Wo, W1, W2, W3, wh);
    bias_cat<<<6, 256>>>(bf, bi, bg, bcat);

    dim3 blk(256);
    dim3 gD(4, 512), gG2(16, 512), gTri(12, 512);
    const int rowsBlocks = MROWS / 8;
    const int scanBlocks = BSZ * SCAN_CH;

    tc_gemm<MODE_TRI><<<gTri, blk, SMEM_BYTES>>>(xh, wh, bcat, bA, bB, bC, nullptr, lbp, DIM, DIM);
    scan_pass1<<<scanBlocks, 512>>>(bA, bB, lFh, lBh, prod, lastF, lastB);
    scan_pass2<<<(BSZ * DIM + 255) / 256, 256>>>(prod, lastF, lastB, CF, CB);
    scan_pass3_rms<<<scanBlocks, 512>>>(bA, lFh, lBh, CF, CB, bC, hgh);
    tc_gemm<MODE_PLAIN><<<gD, blk, SMEM_BYTES>>>(hgh, WoT, bo, bB, nullptr, nullptr, nullptr, nullptr, DIM, DIM);
    ln_add<<<rowsBlocks, 256>>>(bB, x, tn_g, tn_b, bC, x1h);
    // fused GLU: p = silu(x1@W1+b1) * (x1@W2+b2)  (one launch, no c materialization)
    tc_gemm<MODE_GLU2><<<gG2, blk, SMEM_BYTES>>>(x1h, W12T, b1, ph, nullptr, nullptr, b2, nullptr, DGLU, DIM);
    tc_gemm<MODE_PLAIN><<<gD, blk, SMEM_BYTES>>>(ph, W3T, b3, bB, nullptr, nullptr, nullptr, nullptr, DIM, DGLU);
    ln_add<<<rowsBlocks, 256>>>(bB, bC, fn_g, fn_b, out, nullptr);
}